// round 4
// baseline (speedup 1.0000x reference)
#include <cuda_runtime.h>
#include <math.h>
#include <stdint.h>

// Problem constants
// B=2, T=2048, D=2048, H=8, DK=256, DV=512, C=64, N=T/C=32
#define TT 2048

// ---------------- scratch (static device memory; no allocs allowed) ----------
__device__ float d_q[(size_t)4096 * 2048];   // (B*T, H*DK) post-GEMM then post-RoPE (q scaled)
__device__ float d_k[(size_t)4096 * 2048];
__device__ float d_v[(size_t)4096 * 4096];   // (B*T, H*DV)
__device__ float d_g[(size_t)4096 * 4096];
__device__ float d_o[(size_t)4096 * 4096];   // retention output -> gated in place
__device__ float d_U[(size_t)512 * 256 * 512]; // per-chunk KV, then prefix states S_n (in place)
__device__ float d_sc[(size_t)512 * 64 * 64];  // decayed attention scores per chunk

// ---------------- generic SGEMM: C[M,N] = A[M,K] (row-major) * B[N,K]^T ------
#define BM 128
#define BN 128
#define BKK 16
#define TM 8
#define TN 8

__global__ __launch_bounds__(256, 2)
void sgemm_abt(const float* __restrict__ A, const float* __restrict__ B,
               float* __restrict__ C, int M, int N, int K)
{
    __shared__ float As[BKK][BM + 4];
    __shared__ float Bs[BKK][BN + 4];
    const int tid = threadIdx.x;
    const int bm = blockIdx.y * BM;
    const int bn = blockIdx.x * BN;
    const int tx = tid & 15;
    const int ty = tid >> 4;

    float acc[TM][TN];
#pragma unroll
    for (int i = 0; i < TM; ++i)
#pragma unroll
        for (int j = 0; j < TN; ++j) acc[i][j] = 0.f;

    for (int k0 = 0; k0 < K; k0 += BKK) {
#pragma unroll
        for (int l = 0; l < 2; ++l) {
            int idx = tid + l * 256;          // 0..511
            int row = idx >> 2;               // 0..127
            int kq = (idx & 3) * 4;           // 0,4,8,12
            float4 va = *(const float4*)(A + (size_t)(bm + row) * K + k0 + kq);
            As[kq + 0][row] = va.x; As[kq + 1][row] = va.y;
            As[kq + 2][row] = va.z; As[kq + 3][row] = va.w;
            float4 vb = *(const float4*)(B + (size_t)(bn + row) * K + k0 + kq);
            Bs[kq + 0][row] = vb.x; Bs[kq + 1][row] = vb.y;
            Bs[kq + 2][row] = vb.z; Bs[kq + 3][row] = vb.w;
        }
        __syncthreads();
#pragma unroll
        for (int kk = 0; kk < BKK; ++kk) {
            float4 a0 = *(const float4*)&As[kk][ty * TM];
            float4 a1 = *(const float4*)&As[kk][ty * TM + 4];
            float4 b0 = *(const float4*)&Bs[kk][tx * TN];
            float4 b1 = *(const float4*)&Bs[kk][tx * TN + 4];
            float ra[TM] = {a0.x, a0.y, a0.z, a0.w, a1.x, a1.y, a1.z, a1.w};
            float rb[TN] = {b0.x, b0.y, b0.z, b0.w, b1.x, b1.y, b1.z, b1.w};
#pragma unroll
            for (int i = 0; i < TM; ++i)
#pragma unroll
                for (int j = 0; j < TN; ++j) acc[i][j] = fmaf(ra[i], rb[j], acc[i][j]);
        }
        __syncthreads();
    }
#pragma unroll
    for (int i = 0; i < TM; ++i) {
        float* cp = C + (size_t)(bm + ty * TM + i) * N + bn + tx * TN;
        *(float4*)(cp)     = make_float4(acc[i][0], acc[i][1], acc[i][2], acc[i][3]);
        *(float4*)(cp + 4) = make_float4(acc[i][4], acc[i][5], acc[i][6], acc[i][7]);
    }
}

// ---------------- RoPE on q and k (q also scaled by DK^-0.5 = 1/16) ----------
__global__ void rope_kernel()
{
    int idx = blockIdx.x * blockDim.x + threadIdx.x; // < 4096*8*128
    int i = idx & 127;           // rotary freq index (half = 128)
    int h = (idx >> 7) & 7;
    int bt = idx >> 10;          // 0..4095
    int t = bt & (TT - 1);

    // inv_freq = 10000^(-i/128); replicate reference f32 rounding of t*inv_freq,
    // then accurate (double) trig to dodge fast-math range-reduction error.
    double invf_d = exp(-(double)i * (9.210340371976184 / 128.0));
    float invf = (float)invf_d;
    float phase = (float)t * invf;
    double sd, cd;
    sincos((double)phase, &sd, &cd);
    float c = (float)cd, s = (float)sd;

    size_t base = (size_t)bt * 2048 + h * 256 + i;
    float x1 = d_q[base], x2 = d_q[base + 128];
    d_q[base]       = (x1 * c - x2 * s) * 0.0625f;
    d_q[base + 128] = (x2 * c + x1 * s) * 0.0625f;
    x1 = d_k[base]; x2 = d_k[base + 128];
    d_k[base]       = x1 * c - x2 * s;
    d_k[base + 128] = x2 * c + x1 * s;
}

// ---------------- Phase A: U[unit] = (k ∘ k_dec)^T @ v  (256x512 per unit) ---
__global__ __launch_bounds__(256)
void chunk_kv_kernel()
{
    __shared__ float As[16][68];   // [c][d]  (64 d-slice)
    __shared__ float Bs[16][132];  // [c][vv] (128 vv-slice)
    const int tid = threadIdx.x;
    const int tile = blockIdx.x;           // 16 tiles: 4 d x 4 vv
    const int unit = blockIdx.y;           // 512 = (b*H+h)*32 + n
    const int d0 = (tile >> 2) * 64;
    const int vv0 = (tile & 3) * 128;
    const int bh = unit >> 5, n = unit & 31;
    const int b = bh >> 3, h = bh & 7;
    const int bt0 = b * TT + n * 64;
    const float logb = logf(1.0f - exp2f(-5.0f - (float)h));
    const int tx = tid & 15, ty = tid >> 4;

    float acc[4][8];
#pragma unroll
    for (int i = 0; i < 4; ++i)
#pragma unroll
        for (int j = 0; j < 8; ++j) acc[i][j] = 0.f;

    for (int c0 = 0; c0 < 64; c0 += 16) {
        {   // A: 16(c) x 64(d), scaled by k_dec = b^(63-c)
            int c = tid >> 4, dq = (tid & 15) * 4;
            float4 a = *(const float4*)&d_k[(size_t)(bt0 + c0 + c) * 2048 + h * 256 + d0 + dq];
            float kd = expf(logb * (float)(63 - (c0 + c)));
            As[c][dq + 0] = a.x * kd; As[c][dq + 1] = a.y * kd;
            As[c][dq + 2] = a.z * kd; As[c][dq + 3] = a.w * kd;
        }
#pragma unroll
        for (int l = 0; l < 2; ++l) {   // B: 16(c) x 128(vv)
            int idx = tid + l * 256;
            int c = idx >> 5, vq = (idx & 31) * 4;
            float4 bv = *(const float4*)&d_v[(size_t)(bt0 + c0 + c) * 4096 + h * 512 + vv0 + vq];
            Bs[c][vq + 0] = bv.x; Bs[c][vq + 1] = bv.y;
            Bs[c][vq + 2] = bv.z; Bs[c][vq + 3] = bv.w;
        }
        __syncthreads();
#pragma unroll
        for (int kk = 0; kk < 16; ++kk) {
            float4 ra = *(const float4*)&As[kk][ty * 4];
            float4 b0 = *(const float4*)&Bs[kk][tx * 8];
            float4 b1 = *(const float4*)&Bs[kk][tx * 8 + 4];
            float a4[4] = {ra.x, ra.y, ra.z, ra.w};
            float b8[8] = {b0.x, b0.y, b0.z, b0.w, b1.x, b1.y, b1.z, b1.w};
#pragma unroll
            for (int i = 0; i < 4; ++i)
#pragma unroll
                for (int j = 0; j < 8; ++j) acc[i][j] = fmaf(a4[i], b8[j], acc[i][j]);
        }
        __syncthreads();
    }
#pragma unroll
    for (int i = 0; i < 4; ++i) {
        size_t base = ((size_t)unit * 256 + d0 + ty * 4 + i) * 512 + vv0 + tx * 8;
        *(float4*)&d_U[base]     = make_float4(acc[i][0], acc[i][1], acc[i][2], acc[i][3]);
        *(float4*)&d_U[base + 4] = make_float4(acc[i][4], acc[i][5], acc[i][6], acc[i][7]);
    }
}

// ---------------- Phase B: in-place decay scan U_n -> S_n (prefix states) ----
__global__ void scan_kernel()
{
    int bh = blockIdx.x >> 9;                          // 0..15
    int e = ((blockIdx.x & 511) << 8) + threadIdx.x;   // 0..131071
    int h = bh & 7;
    float logb = logf(1.0f - exp2f(-5.0f - (float)h));
    float cd = expf(logb * 64.0f);
    size_t base = (size_t)bh * (32u * 131072u) + e;
    float p = 0.f;
#pragma unroll
    for (int n = 0; n < 32; ++n) {
        size_t idx = base + (size_t)n * 131072;
        float u = d_U[idx];
        d_U[idx] = p;       // slot n now holds state BEFORE chunk n
        p = p * cd + u;
    }
}

// ---------------- scores: d_sc[unit] = Dmask ∘ (Q @ K^T), 64x64 --------------
__global__ __launch_bounds__(256)
void scores_kernel()
{
    __shared__ float Qs[32][68];
    __shared__ float Ks[32][68];
    const int unit = blockIdx.x;
    const int bh = unit >> 5, n = unit & 31;
    const int b = bh >> 3, h = bh & 7;
    const int bt0 = b * TT + n * 64;
    const float logb = logf(1.0f - exp2f(-5.0f - (float)h));
    const int tid = threadIdx.x, tx = tid & 15, ty = tid >> 4;

    float acc[4][4];
#pragma unroll
    for (int i = 0; i < 4; ++i)
#pragma unroll
        for (int j = 0; j < 4; ++j) acc[i][j] = 0.f;

    for (int k0 = 0; k0 < 256; k0 += 32) {
#pragma unroll
        for (int l = 0; l < 2; ++l) {
            int idx = tid + l * 256;        // 0..511
            int row = idx >> 3;             // 0..63
            int kq = (idx & 7) * 4;         // 0..28
            float4 qv = *(const float4*)&d_q[(size_t)(bt0 + row) * 2048 + h * 256 + k0 + kq];
            Qs[kq + 0][row] = qv.x; Qs[kq + 1][row] = qv.y;
            Qs[kq + 2][row] = qv.z; Qs[kq + 3][row] = qv.w;
            float4 kv = *(const float4*)&d_k[(size_t)(bt0 + row) * 2048 + h * 256 + k0 + kq];
            Ks[kq + 0][row] = kv.x; Ks[kq + 1][row] = kv.y;
            Ks[kq + 2][row] = kv.z; Ks[kq + 3][row] = kv.w;
        }
        __syncthreads();
#pragma unroll
        for (int kk = 0; kk < 32; ++kk) {
            float4 ra = *(const float4*)&Qs[kk][ty * 4];
            float4 rb = *(const float4*)&Ks[kk][tx * 4];
            float a4[4] = {ra.x, ra.y, ra.z, ra.w};
            float b4[4] = {rb.x, rb.y, rb.z, rb.w};
#pragma unroll
            for (int i = 0; i < 4; ++i)
#pragma unroll
                for (int j = 0; j < 4; ++j) acc[i][j] = fmaf(a4[i], b4[j], acc[i][j]);
        }
        __syncthreads();
    }
#pragma unroll
    for (int ii = 0; ii < 4; ++ii)
#pragma unroll
        for (int jj = 0; jj < 4; ++jj) {
            int i = ty * 4 + ii, j = tx * 4 + jj, m = i - j;
            float val = (m >= 0) ? acc[ii][jj] * expf(logb * (float)m) : 0.f;
            d_sc[((size_t)unit * 64 + i) * 64 + j] = val;
        }
}

// ---------------- Phase C: o = (q∘q_dec)@S_n + scores@V  (fused K=320 GEMM) --
__global__ __launch_bounds__(256)
void chunk_out_kernel()
{
    __shared__ float As[16][68];   // [k][i]
    __shared__ float Bs[16][132];  // [k][vv]
    const int tid = threadIdx.x;
    const int vv0 = blockIdx.x * 128;   // 4 tiles
    const int unit = blockIdx.y;        // 512
    const int bh = unit >> 5, n = unit & 31;
    const int b = bh >> 3, h = bh & 7;
    const int bt0 = b * TT + n * 64;
    const float logb = logf(1.0f - exp2f(-5.0f - (float)h));
    const int tx = tid & 15, ty = tid >> 4;

    float acc[4][8];
#pragma unroll
    for (int i = 0; i < 4; ++i)
#pragma unroll
        for (int j = 0; j < 8; ++j) acc[i][j] = 0.f;

    for (int s = 0; s < 20; ++s) {
        const int k0 = s * 16;
        {   // A: 64(i) x 16(k)
            int ar = tid >> 2, kq = (tid & 3) * 4;
            float4 a;
            if (k0 < 256) {
                a = *(const float4*)&d_q[(size_t)(bt0 + ar) * 2048 + h * 256 + k0 + kq];
                float qd = expf(logb * (float)(ar + 1));
                a.x *= qd; a.y *= qd; a.z *= qd; a.w *= qd;
            } else {
                a = *(const float4*)&d_sc[((size_t)unit * 64 + ar) * 64 + (k0 - 256) + kq];
            }
            As[kq + 0][ar] = a.x; As[kq + 1][ar] = a.y;
            As[kq + 2][ar] = a.z; As[kq + 3][ar] = a.w;
        }
#pragma unroll
        for (int l = 0; l < 2; ++l) {   // B: 16(k) x 128(vv)
            int idx = tid + l * 256;
            int c = idx >> 5, vq = (idx & 31) * 4;
            float4 bv;
            if (k0 < 256)
                bv = *(const float4*)&d_U[((size_t)unit * 256 + k0 + c) * 512 + vv0 + vq];
            else
                bv = *(const float4*)&d_v[(size_t)(bt0 + (k0 - 256) + c) * 4096 + h * 512 + vv0 + vq];
            Bs[c][vq + 0] = bv.x; Bs[c][vq + 1] = bv.y;
            Bs[c][vq + 2] = bv.z; Bs[c][vq + 3] = bv.w;
        }
        __syncthreads();
#pragma unroll
        for (int kk = 0; kk < 16; ++kk) {
            float4 ra = *(const float4*)&As[kk][ty * 4];
            float4 b0 = *(const float4*)&Bs[kk][tx * 8];
            float4 b1 = *(const float4*)&Bs[kk][tx * 8 + 4];
            float a4[4] = {ra.x, ra.y, ra.z, ra.w};
            float b8[8] = {b0.x, b0.y, b0.z, b0.w, b1.x, b1.y, b1.z, b1.w};
#pragma unroll
            for (int i = 0; i < 4; ++i)
#pragma unroll
                for (int j = 0; j < 8; ++j) acc[i][j] = fmaf(a4[i], b8[j], acc[i][j]);
        }
        __syncthreads();
    }
#pragma unroll
    for (int i = 0; i < 4; ++i) {
        size_t base = (size_t)(bt0 + ty * 4 + i) * 4096 + h * 512 + vv0 + tx * 8;
        *(float4*)&d_o[base]     = make_float4(acc[i][0], acc[i][1], acc[i][2], acc[i][3]);
        *(float4*)&d_o[base + 4] = make_float4(acc[i][4], acc[i][5], acc[i][6], acc[i][7]);
    }
}

// ---------------- rmsnorm over DV + silu(g) gating, in place on d_o ----------
__global__ void gate_norm_kernel(const float* __restrict__ gw)
{
    __shared__ float red[4];
    const int row = blockIdx.x;           // bt*8 + h (32768 rows)
    const int bt = row >> 3, h = row & 7;
    const size_t base = (size_t)bt * 4096 + h * 512;
    const int tid = threadIdx.x;          // 128 threads x 4 elems

    float4 ov = *(const float4*)&d_o[base + tid * 4];
    float ss = ov.x * ov.x + ov.y * ov.y + ov.z * ov.z + ov.w * ov.w;
#pragma unroll
    for (int off = 16; off; off >>= 1) ss += __shfl_xor_sync(0xffffffffu, ss, off);
    if ((tid & 31) == 0) red[tid >> 5] = ss;
    __syncthreads();
    float tot = red[0] + red[1] + red[2] + red[3];
    float inv = rsqrtf(tot * (1.0f / 512.0f) + 1e-5f);

    float4 gv = *(const float4*)&d_g[base + tid * 4];
    float4 w  = *(const float4*)&gw[tid * 4];
    float4 out;
    out.x = ov.x * inv * w.x * (gv.x / (1.f + expf(-gv.x)));
    out.y = ov.y * inv * w.y * (gv.y / (1.f + expf(-gv.y)));
    out.z = ov.z * inv * w.z * (gv.z / (1.f + expf(-gv.z)));
    out.w = ov.w * inv * w.w * (gv.w / (1.f + expf(-gv.w)));
    *(float4*)&d_o[base + tid * 4] = out;
}

// ---------------- launch ------------------------------------------------------
extern "C" void kernel_launch(void* const* d_in, const int* in_sizes, int n_in,
                              void* d_out, int out_size)
{
    const float* X  = (const float*)d_in[0];
    const float* Wq = (const float*)d_in[1];
    const float* Wk = (const float*)d_in[2];
    const float* Wv = (const float*)d_in[3];
    const float* Wg = (const float*)d_in[4];
    const float* Wo = (const float*)d_in[5];
    const float* gw = (const float*)d_in[6];
    float* out = (float*)d_out;

    float *q, *k, *v, *g, *o;
    cudaGetSymbolAddress((void**)&q, d_q);
    cudaGetSymbolAddress((void**)&k, d_k);
    cudaGetSymbolAddress((void**)&v, d_v);
    cudaGetSymbolAddress((void**)&g, d_g);
    cudaGetSymbolAddress((void**)&o, d_o);

    // Projections: q,k (4096x2048), v,g (4096x4096); K=2048
    sgemm_abt<<<dim3(16, 32), 256>>>(X, Wq, q, 4096, 2048, 2048);
    sgemm_abt<<<dim3(16, 32), 256>>>(X, Wk, k, 4096, 2048, 2048);
    sgemm_abt<<<dim3(32, 32), 256>>>(X, Wv, v, 4096, 4096, 2048);
    sgemm_abt<<<dim3(32, 32), 256>>>(X, Wg, g, 4096, 4096, 2048);

    rope_kernel<<<16384, 256>>>();

    chunk_kv_kernel<<<dim3(16, 512), 256>>>();   // U_n
    scan_kernel<<<8192, 256>>>();                // U_n -> S_n (in place)
    scores_kernel<<<512, 256>>>();               // Dmask ∘ QK^T
    chunk_out_kernel<<<dim3(4, 512), 256>>>();   // o

    gate_norm_kernel<<<32768, 128>>>(gw);

    // Output projection: (4096 x 4096) @ Wo^T -> (4096 x 2048)
    sgemm_abt<<<dim3(16, 32), 256>>>(o, Wo, out, 4096, 2048, 4096);
}

// round 5
// speedup vs baseline: 1.6872x; 1.6872x over previous
#include <cuda_runtime.h>
#include <cuda_bf16.h>
#include <math.h>
#include <stdint.h>

// Problem constants: B=2, T=2048, D=2048, H=8, DK=256, DV=512, C=64, N=32
#define TT 2048

// ---------------- scratch (static device memory; no allocs allowed) ----------
__device__ float d_q[(size_t)4096 * 2048];
__device__ float d_k[(size_t)4096 * 2048];
__device__ float d_v[(size_t)4096 * 4096];
__device__ float d_g[(size_t)4096 * 4096];
__device__ float d_o[(size_t)4096 * 4096];
__device__ float d_U[(size_t)512 * 256 * 512]; // per-chunk KV -> prefix states (in place)
__device__ float d_sc[(size_t)512 * 64 * 64];  // decayed attention scores
__device__ float d_ropec[2048 * 128];
__device__ float d_ropes[2048 * 128];

// =====================================================================
// Split-bf16 tensor-core GEMM: C[M,N] = A[M,K] (row-major) * B[N,K]^T
// a = hi + lo (bf16 each); C += hh + hl + lh  (ll dropped, ~2^-18 rel)
// Block 128x128, K-step 32, 8 warps of 64x32.
// =====================================================================
#define GSTRIDE 40   // bf16 elems per smem row (32 + 8 pad) -> 80B, LDSM conflict-free

__device__ __forceinline__ void ldsm_x4(uint32_t& r0, uint32_t& r1, uint32_t& r2, uint32_t& r3, uint32_t addr) {
    asm volatile("ldmatrix.sync.aligned.m8n8.x4.shared.b16 {%0,%1,%2,%3}, [%4];\n"
                 : "=r"(r0), "=r"(r1), "=r"(r2), "=r"(r3) : "r"(addr));
}
__device__ __forceinline__ void mma16816(float* c, const uint32_t* a, const uint32_t* b) {
    asm volatile("mma.sync.aligned.m16n8k16.row.col.f32.bf16.bf16.f32 "
                 "{%0,%1,%2,%3},{%4,%5,%6,%7},{%8,%9},{%0,%1,%2,%3};\n"
                 : "+f"(c[0]), "+f"(c[1]), "+f"(c[2]), "+f"(c[3])
                 : "r"(a[0]), "r"(a[1]), "r"(a[2]), "r"(a[3]), "r"(b[0]), "r"(b[1]));
}
__device__ __forceinline__ void cvt_store4(__nv_bfloat16* hi, __nv_bfloat16* lo, int off, float4 v) {
    __nv_bfloat16 hx = __float2bfloat16(v.x), hy = __float2bfloat16(v.y);
    __nv_bfloat16 hz = __float2bfloat16(v.z), hw = __float2bfloat16(v.w);
    *(__nv_bfloat162*)(hi + off)     = __halves2bfloat162(hx, hy);
    *(__nv_bfloat162*)(hi + off + 2) = __halves2bfloat162(hz, hw);
    *(__nv_bfloat162*)(lo + off)     = __halves2bfloat162(
        __float2bfloat16(v.x - __bfloat162float(hx)), __float2bfloat16(v.y - __bfloat162float(hy)));
    *(__nv_bfloat162*)(lo + off + 2) = __halves2bfloat162(
        __float2bfloat16(v.z - __bfloat162float(hz)), __float2bfloat16(v.w - __bfloat162float(hw)));
}

__global__ __launch_bounds__(256, 1)
void gemm_bf16s(const float* __restrict__ A, const float* __restrict__ B,
                float* __restrict__ C, int M, int N, int K)
{
    __shared__ __nv_bfloat16 Ash[128 * GSTRIDE];
    __shared__ __nv_bfloat16 Asl[128 * GSTRIDE];
    __shared__ __nv_bfloat16 Bsh[128 * GSTRIDE];
    __shared__ __nv_bfloat16 Bsl[128 * GSTRIDE];

    const int tid = threadIdx.x;
    const int warp = tid >> 5, lane = tid & 31;
    const int wm = warp >> 2, wn = warp & 3;       // warp tile: rows wm*64, cols wn*32
    const int bm = blockIdx.y * 128, bn = blockIdx.x * 128;

    const uint32_t ah_base = (uint32_t)__cvta_generic_to_shared(Ash);
    const uint32_t al_base = (uint32_t)__cvta_generic_to_shared(Asl);
    const uint32_t bh_base = (uint32_t)__cvta_generic_to_shared(Bsh);
    const uint32_t bl_base = (uint32_t)__cvta_generic_to_shared(Bsl);

    float acc[4][4][4];
#pragma unroll
    for (int i = 0; i < 4; ++i)
#pragma unroll
        for (int j = 0; j < 4; ++j)
#pragma unroll
            for (int e = 0; e < 4; ++e) acc[i][j][e] = 0.f;

    // ldmatrix lane addressing (element offsets within a tile, bf16 units)
    const int a_r = (lane & 15), a_c8 = ((lane >> 4) << 3);
    const int b_r = ((lane >> 4) << 3) + (lane & 7), b_c8 = (((lane >> 3) & 1) << 3);

    for (int k0 = 0; k0 < K; k0 += 32) {
        __syncthreads();
#pragma unroll
        for (int l = 0; l < 4; ++l) {
            int idx = tid + l * 256;            // 0..1023
            int row = idx >> 3;                 // 0..127
            int kq = (idx & 7) * 4;             // 0..28
            float4 va = *(const float4*)(A + (size_t)(bm + row) * K + k0 + kq);
            cvt_store4(Ash, Asl, row * GSTRIDE + kq, va);
            float4 vb = *(const float4*)(B + (size_t)(bn + row) * K + k0 + kq);
            cvt_store4(Bsh, Bsl, row * GSTRIDE + kq, vb);
        }
        __syncthreads();

#pragma unroll
        for (int ks = 0; ks < 2; ++ks) {
            uint32_t ah[4][4], al[4][4], bh[4][2], bl[4][2];
#pragma unroll
            for (int mt = 0; mt < 4; ++mt) {
                int off = ((wm * 64 + mt * 16 + a_r) * GSTRIDE + ks * 16 + a_c8) * 2;
                ldsm_x4(ah[mt][0], ah[mt][1], ah[mt][2], ah[mt][3], ah_base + off);
                ldsm_x4(al[mt][0], al[mt][1], al[mt][2], al[mt][3], al_base + off);
            }
#pragma unroll
            for (int p = 0; p < 2; ++p) {
                int off = ((wn * 32 + p * 16 + b_r) * GSTRIDE + ks * 16 + b_c8) * 2;
                ldsm_x4(bh[2 * p][0], bh[2 * p][1], bh[2 * p + 1][0], bh[2 * p + 1][1], bh_base + off);
                ldsm_x4(bl[2 * p][0], bl[2 * p][1], bl[2 * p + 1][0], bl[2 * p + 1][1], bl_base + off);
            }
#pragma unroll
            for (int mt = 0; mt < 4; ++mt)
#pragma unroll
                for (int nt = 0; nt < 4; ++nt) {
                    mma16816(acc[mt][nt], ah[mt], bh[nt]);  // hi*hi
                    mma16816(acc[mt][nt], ah[mt], bl[nt]);  // hi*lo
                    mma16816(acc[mt][nt], al[mt], bh[nt]);  // lo*hi
                }
        }
    }

    // epilogue: d0,d1 -> (row, col..col+1); d2,d3 -> (row+8, ...)
#pragma unroll
    for (int mt = 0; mt < 4; ++mt)
#pragma unroll
        for (int nt = 0; nt < 4; ++nt) {
            int row = bm + wm * 64 + mt * 16 + (lane >> 2);
            int col = bn + wn * 32 + nt * 8 + (lane & 3) * 2;
            *(float2*)(C + (size_t)row * N + col)       = make_float2(acc[mt][nt][0], acc[mt][nt][1]);
            *(float2*)(C + (size_t)(row + 8) * N + col) = make_float2(acc[mt][nt][2], acc[mt][nt][3]);
        }
}

// ---------------- RoPE table (accurate fp64 trig, computed once per launch) --
__global__ void rope_table_kernel()
{
    int idx = blockIdx.x * blockDim.x + threadIdx.x;   // < 2048*128
    int i = idx & 127, t = idx >> 7;
    double invf_d = exp(-(double)i * (9.210340371976184 / 128.0));
    float phase = (float)t * (float)invf_d;            // replicate f32 rounding of reference
    double sd, cd;
    sincos((double)phase, &sd, &cd);
    d_ropec[idx] = (float)cd;
    d_ropes[idx] = (float)sd;
}

// ---------------- RoPE on q and k (q also scaled by 1/16) --------------------
__global__ void rope_kernel()
{
    int idx = blockIdx.x * blockDim.x + threadIdx.x;   // < 4096*8*128
    int i = idx & 127;
    int h = (idx >> 7) & 7;
    int bt = idx >> 10;
    int t = bt & (TT - 1);
    float c = d_ropec[(t << 7) + i], s = d_ropes[(t << 7) + i];

    size_t base = (size_t)bt * 2048 + h * 256 + i;
    float x1 = d_q[base], x2 = d_q[base + 128];
    d_q[base]       = (x1 * c - x2 * s) * 0.0625f;
    d_q[base + 128] = (x2 * c + x1 * s) * 0.0625f;
    x1 = d_k[base]; x2 = d_k[base + 128];
    d_k[base]       = x1 * c - x2 * s;
    d_k[base + 128] = x2 * c + x1 * s;
}

// ---------------- Phase A: U[unit] = (k ∘ k_dec)^T @ v  ----------------------
__global__ __launch_bounds__(256)
void chunk_kv_kernel()
{
    __shared__ float As[16][68];
    __shared__ float Bs[16][132];
    const int tid = threadIdx.x;
    const int tile = blockIdx.x;           // 16 tiles: 4 d x 4 vv
    const int unit = blockIdx.y;           // 512
    const int d0 = (tile >> 2) * 64;
    const int vv0 = (tile & 3) * 128;
    const int bh = unit >> 5, n = unit & 31;
    const int b = bh >> 3, h = bh & 7;
    const int bt0 = b * TT + n * 64;
    const float logb = logf(1.0f - exp2f(-5.0f - (float)h));
    const int tx = tid & 15, ty = tid >> 4;

    float acc[4][8];
#pragma unroll
    for (int i = 0; i < 4; ++i)
#pragma unroll
        for (int j = 0; j < 8; ++j) acc[i][j] = 0.f;

    for (int c0 = 0; c0 < 64; c0 += 16) {
        {
            int c = tid >> 4, dq = (tid & 15) * 4;
            float4 a = *(const float4*)&d_k[(size_t)(bt0 + c0 + c) * 2048 + h * 256 + d0 + dq];
            float kd = expf(logb * (float)(63 - (c0 + c)));
            As[c][dq + 0] = a.x * kd; As[c][dq + 1] = a.y * kd;
            As[c][dq + 2] = a.z * kd; As[c][dq + 3] = a.w * kd;
        }
#pragma unroll
        for (int l = 0; l < 2; ++l) {
            int idx = tid + l * 256;
            int c = idx >> 5, vq = (idx & 31) * 4;
            float4 bv = *(const float4*)&d_v[(size_t)(bt0 + c0 + c) * 4096 + h * 512 + vv0 + vq];
            Bs[c][vq + 0] = bv.x; Bs[c][vq + 1] = bv.y;
            Bs[c][vq + 2] = bv.z; Bs[c][vq + 3] = bv.w;
        }
        __syncthreads();
#pragma unroll
        for (int kk = 0; kk < 16; ++kk) {
            float4 ra = *(const float4*)&As[kk][ty * 4];
            float4 b0 = *(const float4*)&Bs[kk][tx * 8];
            float4 b1 = *(const float4*)&Bs[kk][tx * 8 + 4];
            float a4[4] = {ra.x, ra.y, ra.z, ra.w};
            float b8[8] = {b0.x, b0.y, b0.z, b0.w, b1.x, b1.y, b1.z, b1.w};
#pragma unroll
            for (int i = 0; i < 4; ++i)
#pragma unroll
                for (int j = 0; j < 8; ++j) acc[i][j] = fmaf(a4[i], b8[j], acc[i][j]);
        }
        __syncthreads();
    }
#pragma unroll
    for (int i = 0; i < 4; ++i) {
        size_t base = ((size_t)unit * 256 + d0 + ty * 4 + i) * 512 + vv0 + tx * 8;
        *(float4*)&d_U[base]     = make_float4(acc[i][0], acc[i][1], acc[i][2], acc[i][3]);
        *(float4*)&d_U[base + 4] = make_float4(acc[i][4], acc[i][5], acc[i][6], acc[i][7]);
    }
}

// ---------------- Phase B: in-place decay scan U_n -> S_n --------------------
__global__ void scan_kernel()
{
    int bh = blockIdx.x >> 9;
    int e = ((blockIdx.x & 511) << 8) + threadIdx.x;
    int h = bh & 7;
    float logb = logf(1.0f - exp2f(-5.0f - (float)h));
    float cd = expf(logb * 64.0f);
    size_t base = (size_t)bh * (32u * 131072u) + e;
    float p = 0.f;
#pragma unroll
    for (int n = 0; n < 32; ++n) {
        size_t idx = base + (size_t)n * 131072;
        float u = d_U[idx];
        d_U[idx] = p;
        p = p * cd + u;
    }
}

// ---------------- scores: Dmask ∘ (Q @ K^T) ----------------------------------
__global__ __launch_bounds__(256)
void scores_kernel()
{
    __shared__ float Qs[32][68];
    __shared__ float Ks[32][68];
    const int unit = blockIdx.x;
    const int bh = unit >> 5, n = unit & 31;
    const int b = bh >> 3, h = bh & 7;
    const int bt0 = b * TT + n * 64;
    const float logb = logf(1.0f - exp2f(-5.0f - (float)h));
    const int tid = threadIdx.x, tx = tid & 15, ty = tid >> 4;

    float acc[4][4];
#pragma unroll
    for (int i = 0; i < 4; ++i)
#pragma unroll
        for (int j = 0; j < 4; ++j) acc[i][j] = 0.f;

    for (int k0 = 0; k0 < 256; k0 += 32) {
#pragma unroll
        for (int l = 0; l < 2; ++l) {
            int idx = tid + l * 256;
            int row = idx >> 3;
            int kq = (idx & 7) * 4;
            float4 qv = *(const float4*)&d_q[(size_t)(bt0 + row) * 2048 + h * 256 + k0 + kq];
            Qs[kq + 0][row] = qv.x; Qs[kq + 1][row] = qv.y;
            Qs[kq + 2][row] = qv.z; Qs[kq + 3][row] = qv.w;
            float4 kv = *(const float4*)&d_k[(size_t)(bt0 + row) * 2048 + h * 256 + k0 + kq];
            Ks[kq + 0][row] = kv.x; Ks[kq + 1][row] = kv.y;
            Ks[kq + 2][row] = kv.z; Ks[kq + 3][row] = kv.w;
        }
        __syncthreads();
#pragma unroll
        for (int kk = 0; kk < 32; ++kk) {
            float4 ra = *(const float4*)&Qs[kk][ty * 4];
            float4 rb = *(const float4*)&Ks[kk][tx * 4];
            float a4[4] = {ra.x, ra.y, ra.z, ra.w};
            float b4[4] = {rb.x, rb.y, rb.z, rb.w};
#pragma unroll
            for (int i = 0; i < 4; ++i)
#pragma unroll
                for (int j = 0; j < 4; ++j) acc[i][j] = fmaf(a4[i], b4[j], acc[i][j]);
        }
        __syncthreads();
    }
#pragma unroll
    for (int ii = 0; ii < 4; ++ii)
#pragma unroll
        for (int jj = 0; jj < 4; ++jj) {
            int i = ty * 4 + ii, j = tx * 4 + jj, m = i - j;
            float val = (m >= 0) ? acc[ii][jj] * expf(logb * (float)m) : 0.f;
            d_sc[((size_t)unit * 64 + i) * 64 + j] = val;
        }
}

// ---------------- Phase C: o = (q∘q_dec)@S_n + scores@V ----------------------
__global__ __launch_bounds__(256)
void chunk_out_kernel()
{
    __shared__ float As[16][68];
    __shared__ float Bs[16][132];
    const int tid = threadIdx.x;
    const int vv0 = blockIdx.x * 128;
    const int unit = blockIdx.y;
    const int bh = unit >> 5, n = unit & 31;
    const int b = bh >> 3, h = bh & 7;
    const int bt0 = b * TT + n * 64;
    const float logb = logf(1.0f - exp2f(-5.0f - (float)h));
    const int tx = tid & 15, ty = tid >> 4;

    float acc[4][8];
#pragma unroll
    for (int i = 0; i < 4; ++i)
#pragma unroll
        for (int j = 0; j < 8; ++j) acc[i][j] = 0.f;

    for (int s = 0; s < 20; ++s) {
        const int k0 = s * 16;
        {
            int ar = tid >> 2, kq = (tid & 3) * 4;
            float4 a;
            if (k0 < 256) {
                a = *(const float4*)&d_q[(size_t)(bt0 + ar) * 2048 + h * 256 + k0 + kq];
                float qd = expf(logb * (float)(ar + 1));
                a.x *= qd; a.y *= qd; a.z *= qd; a.w *= qd;
            } else {
                a = *(const float4*)&d_sc[((size_t)unit * 64 + ar) * 64 + (k0 - 256) + kq];
            }
            As[kq + 0][ar] = a.x; As[kq + 1][ar] = a.y;
            As[kq + 2][ar] = a.z; As[kq + 3][ar] = a.w;
        }
#pragma unroll
        for (int l = 0; l < 2; ++l) {
            int idx = tid + l * 256;
            int c = idx >> 5, vq = (idx & 31) * 4;
            float4 bv;
            if (k0 < 256)
                bv = *(const float4*)&d_U[((size_t)unit * 256 + k0 + c) * 512 + vv0 + vq];
            else
                bv = *(const float4*)&d_v[(size_t)(bt0 + (k0 - 256) + c) * 4096 + h * 512 + vv0 + vq];
            Bs[c][vq + 0] = bv.x; Bs[c][vq + 1] = bv.y;
            Bs[c][vq + 2] = bv.z; Bs[c][vq + 3] = bv.w;
        }
        __syncthreads();
#pragma unroll
        for (int kk = 0; kk < 16; ++kk) {
            float4 ra = *(const float4*)&As[kk][ty * 4];
            float4 b0 = *(const float4*)&Bs[kk][tx * 8];
            float4 b1 = *(const float4*)&Bs[kk][tx * 8 + 4];
            float a4[4] = {ra.x, ra.y, ra.z, ra.w};
            float b8[8] = {b0.x, b0.y, b0.z, b0.w, b1.x, b1.y, b1.z, b1.w};
#pragma unroll
            for (int i = 0; i < 4; ++i)
#pragma unroll
                for (int j = 0; j < 8; ++j) acc[i][j] = fmaf(a4[i], b8[j], acc[i][j]);
        }
        __syncthreads();
    }
#pragma unroll
    for (int i = 0; i < 4; ++i) {
        size_t base = (size_t)(bt0 + ty * 4 + i) * 4096 + h * 512 + vv0 + tx * 8;
        *(float4*)&d_o[base]     = make_float4(acc[i][0], acc[i][1], acc[i][2], acc[i][3]);
        *(float4*)&d_o[base + 4] = make_float4(acc[i][4], acc[i][5], acc[i][6], acc[i][7]);
    }
}

// ---------------- rmsnorm over DV + silu(g) gating, in place on d_o ----------
__global__ void gate_norm_kernel(const float* __restrict__ gw)
{
    __shared__ float red[4];
    const int row = blockIdx.x;
    const int bt = row >> 3, h = row & 7;
    const size_t base = (size_t)bt * 4096 + h * 512;
    const int tid = threadIdx.x;

    float4 ov = *(const float4*)&d_o[base + tid * 4];
    float ss = ov.x * ov.x + ov.y * ov.y + ov.z * ov.z + ov.w * ov.w;
#pragma unroll
    for (int off = 16; off; off >>= 1) ss += __shfl_xor_sync(0xffffffffu, ss, off);
    if ((tid & 31) == 0) red[tid >> 5] = ss;
    __syncthreads();
    float tot = red[0] + red[1] + red[2] + red[3];
    float inv = rsqrtf(tot * (1.0f / 512.0f) + 1e-5f);

    float4 gv = *(const float4*)&d_g[base + tid * 4];
    float4 w  = *(const float4*)&gw[tid * 4];
    float4 out;
    out.x = ov.x * inv * w.x * (gv.x / (1.f + expf(-gv.x)));
    out.y = ov.y * inv * w.y * (gv.y / (1.f + expf(-gv.y)));
    out.z = ov.z * inv * w.z * (gv.z / (1.f + expf(-gv.z)));
    out.w = ov.w * inv * w.w * (gv.w / (1.f + expf(-gv.w)));
    *(float4*)&d_o[base + tid * 4] = out;
}

// ---------------- launch ------------------------------------------------------
extern "C" void kernel_launch(void* const* d_in, const int* in_sizes, int n_in,
                              void* d_out, int out_size)
{
    const float* X  = (const float*)d_in[0];
    const float* Wq = (const float*)d_in[1];
    const float* Wk = (const float*)d_in[2];
    const float* Wv = (const float*)d_in[3];
    const float* Wg = (const float*)d_in[4];
    const float* Wo = (const float*)d_in[5];
    const float* gw = (const float*)d_in[6];
    float* out = (float*)d_out;

    float *q, *k, *v, *g, *o;
    cudaGetSymbolAddress((void**)&q, d_q);
    cudaGetSymbolAddress((void**)&k, d_k);
    cudaGetSymbolAddress((void**)&v, d_v);
    cudaGetSymbolAddress((void**)&g, d_g);
    cudaGetSymbolAddress((void**)&o, d_o);

    rope_table_kernel<<<1024, 256>>>();

    // Projections on tensor cores (split-bf16)
    gemm_bf16s<<<dim3(16, 32), 256>>>(X, Wq, q, 4096, 2048, 2048);
    gemm_bf16s<<<dim3(16, 32), 256>>>(X, Wk, k, 4096, 2048, 2048);
    gemm_bf16s<<<dim3(32, 32), 256>>>(X, Wv, v, 4096, 4096, 2048);
    gemm_bf16s<<<dim3(32, 32), 256>>>(X, Wg, g, 4096, 4096, 2048);

    rope_kernel<<<16384, 256>>>();

    chunk_kv_kernel<<<dim3(16, 512), 256>>>();
    scan_kernel<<<8192, 256>>>();
    scores_kernel<<<512, 256>>>();
    chunk_out_kernel<<<dim3(4, 512), 256>>>();

    gate_norm_kernel<<<32768, 128>>>(gw);

    gemm_bf16s<<<dim3(16, 32), 256>>>(o, Wo, out, 4096, 2048, 4096);
}

// round 7
// speedup vs baseline: 1.8251x; 1.0818x over previous
#include <cuda_runtime.h>
#include <cuda_bf16.h>
#include <math.h>
#include <stdint.h>

// Problem constants: B=2, T=2048, D=2048, H=8, DK=256, DV=512, C=64, N=32
#define TT 2048

// ---------------- scratch (static device memory; no allocs allowed) ----------
__device__ float d_q[(size_t)4096 * 2048];
__device__ float d_k[(size_t)4096 * 2048];
__device__ float d_v[(size_t)4096 * 4096];
__device__ float d_g[(size_t)4096 * 4096];
__device__ float d_o[(size_t)4096 * 4096];
__device__ float d_U[(size_t)512 * 256 * 512]; // per-chunk KV -> prefix states (in place)
__device__ float d_sc[(size_t)512 * 64 * 64];  // decayed attention scores
__device__ float d_ropec[2048 * 128];
__device__ float d_ropes[2048 * 128];

// bf16 hi/lo split operands for tensor-core GEMMs
__device__ __nv_bfloat16 sX_h[(size_t)4096 * 2048],  sX_l[(size_t)4096 * 2048];
__device__ __nv_bfloat16 sWq_h[(size_t)2048 * 2048], sWq_l[(size_t)2048 * 2048];
__device__ __nv_bfloat16 sWk_h[(size_t)2048 * 2048], sWk_l[(size_t)2048 * 2048];
__device__ __nv_bfloat16 sWv_h[(size_t)4096 * 2048], sWv_l[(size_t)4096 * 2048];
__device__ __nv_bfloat16 sWg_h[(size_t)4096 * 2048], sWg_l[(size_t)4096 * 2048];
__device__ __nv_bfloat16 sWo_h[(size_t)2048 * 4096], sWo_l[(size_t)2048 * 4096];
__device__ __nv_bfloat16 sO_h[(size_t)4096 * 4096],  sO_l[(size_t)4096 * 4096];

// ---------------- fp32 -> bf16 hi/lo split (one-time per operand) ------------
__global__ void split_kernel(const float* __restrict__ src,
                             __nv_bfloat16* __restrict__ hi,
                             __nv_bfloat16* __restrict__ lo, int n4)
{
    int i = blockIdx.x * blockDim.x + threadIdx.x;
    if (i >= n4) return;
    float4 v = ((const float4*)src)[i];
    __nv_bfloat16 hx = __float2bfloat16(v.x), hy = __float2bfloat16(v.y);
    __nv_bfloat16 hz = __float2bfloat16(v.z), hw = __float2bfloat16(v.w);
    __nv_bfloat162 h0 = __halves2bfloat162(hx, hy), h1 = __halves2bfloat162(hz, hw);
    __nv_bfloat162 l0 = __halves2bfloat162(__float2bfloat16(v.x - __bfloat162float(hx)),
                                           __float2bfloat16(v.y - __bfloat162float(hy)));
    __nv_bfloat162 l1 = __halves2bfloat162(__float2bfloat16(v.z - __bfloat162float(hz)),
                                           __float2bfloat16(v.w - __bfloat162float(hw)));
    ((__nv_bfloat162*)hi)[i * 2]     = h0;
    ((__nv_bfloat162*)hi)[i * 2 + 1] = h1;
    ((__nv_bfloat162*)lo)[i * 2]     = l0;
    ((__nv_bfloat162*)lo)[i * 2 + 1] = l1;
}

// =====================================================================
// bf16 tensor-core GEMM over virtual K' = 3K:
//   seg0: Ah*Bh   seg1: Al*Bh   seg2: Ah*Bl   =>  C ~= A*B^T (fp32, ll dropped)
// Block 128x128, K-step 32, 8 warps of 64x32, 2-stage cp.async pipeline.
// =====================================================================
#define GSTRIDE 40   // bf16 elems per smem row (32 + 8 pad) -> 80B, LDSM conflict-free

__device__ __forceinline__ void ldsm_x4(uint32_t& r0, uint32_t& r1, uint32_t& r2, uint32_t& r3, uint32_t addr) {
    asm volatile("ldmatrix.sync.aligned.m8n8.x4.shared.b16 {%0,%1,%2,%3}, [%4];\n"
                 : "=r"(r0), "=r"(r1), "=r"(r2), "=r"(r3) : "r"(addr));
}
__device__ __forceinline__ void mma16816(float* c, const uint32_t* a, const uint32_t* b) {
    asm volatile("mma.sync.aligned.m16n8k16.row.col.f32.bf16.bf16.f32 "
                 "{%0,%1,%2,%3},{%4,%5,%6,%7},{%8,%9},{%0,%1,%2,%3};\n"
                 : "+f"(c[0]), "+f"(c[1]), "+f"(c[2]), "+f"(c[3])
                 : "r"(a[0]), "r"(a[1]), "r"(a[2]), "r"(a[3]), "r"(b[0]), "r"(b[1]));
}
__device__ __forceinline__ void cp16(uint32_t dst, const void* src) {
    asm volatile("cp.async.cg.shared.global [%0], [%1], 16;\n" :: "r"(dst), "l"(src));
}

__global__ __launch_bounds__(256)
void gemm_bf16v(const __nv_bfloat16* __restrict__ Ah, const __nv_bfloat16* __restrict__ Al,
                const __nv_bfloat16* __restrict__ Bh, const __nv_bfloat16* __restrict__ Bl,
                float* __restrict__ C, int M, int N, int K)
{
    __shared__ __nv_bfloat16 SA[2][128 * GSTRIDE];
    __shared__ __nv_bfloat16 SB[2][128 * GSTRIDE];

    const int tid = threadIdx.x;
    const int warp = tid >> 5, lane = tid & 31;
    const int wm = warp >> 2, wn = warp & 3;
    const int bm = blockIdx.y * 128, bn = blockIdx.x * 128;

    const int kseg = K >> 5;          // k-steps per segment
    const int nk = 3 * kseg;          // virtual k-steps

    const uint32_t sa0 = (uint32_t)__cvta_generic_to_shared(&SA[0][0]);
    const uint32_t sb0 = (uint32_t)__cvta_generic_to_shared(&SB[0][0]);
    const uint32_t stage_bytes = 128 * GSTRIDE * 2;

    // producer addressing: 512 16B-chunks per tile, 2 per thread
    const int p_row = tid >> 2;             // 0..63 (x2 via l)
    const int p_ch  = (tid & 3) << 3;       // bf16 elem offset 0,8,16,24

    float acc[4][4][4];
#pragma unroll
    for (int i = 0; i < 4; ++i)
#pragma unroll
        for (int j = 0; j < 4; ++j)
#pragma unroll
            for (int e = 0; e < 4; ++e) acc[i][j][e] = 0.f;

    const int a_r = (lane & 15), a_c8 = ((lane >> 4) << 3);
    const int b_r = ((lane >> 4) << 3) + (lane & 7), b_c8 = (((lane >> 3) & 1) << 3);

    auto issue = [&](int ks) {
        int seg = ks / kseg;
        const __nv_bfloat16* Asel = (seg == 1) ? Al : Ah;
        const __nv_bfloat16* Bsel = (seg == 2) ? Bl : Bh;
        int k0 = (ks - seg * kseg) << 5;
        int s = ks & 1;
#pragma unroll
        for (int l = 0; l < 2; ++l) {
            int row = p_row + l * 64;
            uint32_t soff = (uint32_t)(row * GSTRIDE + p_ch) * 2 + s * stage_bytes;
            cp16(sa0 + soff, Asel + (size_t)(bm + row) * K + k0 + p_ch);
            cp16(sb0 + soff, Bsel + (size_t)(bn + row) * K + k0 + p_ch);
        }
        asm volatile("cp.async.commit_group;\n");
    };

    issue(0);
    for (int ks = 0; ks < nk; ++ks) {
        if (ks + 1 < nk) {
            issue(ks + 1);
            asm volatile("cp.async.wait_group 1;\n");
        } else {
            asm volatile("cp.async.wait_group 0;\n");
        }
        __syncthreads();

        const int s = ks & 1;
        const uint32_t sa = sa0 + s * stage_bytes;
        const uint32_t sb = sb0 + s * stage_bytes;
#pragma unroll
        for (int kh = 0; kh < 2; ++kh) {
            uint32_t af[4][4], bf[4][2];
#pragma unroll
            for (int mt = 0; mt < 4; ++mt) {
                int off = ((wm * 64 + mt * 16 + a_r) * GSTRIDE + kh * 16 + a_c8) * 2;
                ldsm_x4(af[mt][0], af[mt][1], af[mt][2], af[mt][3], sa + off);
            }
#pragma unroll
            for (int p = 0; p < 2; ++p) {
                int off = ((wn * 32 + p * 16 + b_r) * GSTRIDE + kh * 16 + b_c8) * 2;
                ldsm_x4(bf[2 * p][0], bf[2 * p][1], bf[2 * p + 1][0], bf[2 * p + 1][1], sb + off);
            }
#pragma unroll
            for (int mt = 0; mt < 4; ++mt)
#pragma unroll
                for (int nt = 0; nt < 4; ++nt)
                    mma16816(acc[mt][nt], af[mt], bf[nt]);
        }
        __syncthreads();
    }

#pragma unroll
    for (int mt = 0; mt < 4; ++mt)
#pragma unroll
        for (int nt = 0; nt < 4; ++nt) {
            int row = bm + wm * 64 + mt * 16 + (lane >> 2);
            int col = bn + wn * 32 + nt * 8 + (lane & 3) * 2;
            *(float2*)(C + (size_t)row * N + col)       = make_float2(acc[mt][nt][0], acc[mt][nt][1]);
            *(float2*)(C + (size_t)(row + 8) * N + col) = make_float2(acc[mt][nt][2], acc[mt][nt][3]);
        }
}

// ---------------- RoPE table (accurate fp64 trig, once per launch) -----------
__global__ void rope_table_kernel()
{
    int idx = blockIdx.x * blockDim.x + threadIdx.x;   // < 2048*128
    int i = idx & 127, t = idx >> 7;
    double invf_d = exp(-(double)i * (9.210340371976184 / 128.0));
    float phase = (float)t * (float)invf_d;            // replicate reference f32 rounding
    double sd, cd;
    sincos((double)phase, &sd, &cd);
    d_ropec[idx] = (float)cd;
    d_ropes[idx] = (float)sd;
}

// ---------------- RoPE on q and k (q also scaled by 1/16) --------------------
__global__ void rope_kernel()
{
    int idx = blockIdx.x * blockDim.x + threadIdx.x;   // < 4096*8*128
    int i = idx & 127;
    int h = (idx >> 7) & 7;
    int bt = idx >> 10;
    int t = bt & (TT - 1);
    float c = d_ropec[(t << 7) + i], s = d_ropes[(t << 7) + i];

    size_t base = (size_t)bt * 2048 + h * 256 + i;
    float x1 = d_q[base], x2 = d_q[base + 128];
    d_q[base]       = (x1 * c - x2 * s) * 0.0625f;
    d_q[base + 128] = (x2 * c + x1 * s) * 0.0625f;
    x1 = d_k[base]; x2 = d_k[base + 128];
    d_k[base]       = x1 * c - x2 * s;
    d_k[base + 128] = x2 * c + x1 * s;
}

// ---------------- Phase A: U[unit] = (k ∘ k_dec)^T @ v  ----------------------
__global__ __launch_bounds__(256)
void chunk_kv_kernel()
{
    __shared__ float As[16][68];
    __shared__ float Bs[16][132];
    const int tid = threadIdx.x;
    const int tile = blockIdx.x;           // 16 tiles: 4 d x 4 vv
    const int unit = blockIdx.y;           // 512
    const int d0 = (tile >> 2) * 64;
    const int vv0 = (tile & 3) * 128;
    const int bh = unit >> 5, n = unit & 31;
    const int b = bh >> 3, h = bh & 7;
    const int bt0 = b * TT + n * 64;
    const float logb = logf(1.0f - exp2f(-5.0f - (float)h));
    const int tx = tid & 15, ty = tid >> 4;

    float acc[4][8];
#pragma unroll
    for (int i = 0; i < 4; ++i)
#pragma unroll
        for (int j = 0; j < 8; ++j) acc[i][j] = 0.f;

    for (int c0 = 0; c0 < 64; c0 += 16) {
        {
            int c = tid >> 4, dq = (tid & 15) * 4;
            float4 a = *(const float4*)&d_k[(size_t)(bt0 + c0 + c) * 2048 + h * 256 + d0 + dq];
            float kd = expf(logb * (float)(63 - (c0 + c)));
            As[c][dq + 0] = a.x * kd; As[c][dq + 1] = a.y * kd;
            As[c][dq + 2] = a.z * kd; As[c][dq + 3] = a.w * kd;
        }
#pragma unroll
        for (int l = 0; l < 2; ++l) {
            int idx = tid + l * 256;
            int c = idx >> 5, vq = (idx & 31) * 4;
            float4 bv = *(const float4*)&d_v[(size_t)(bt0 + c0 + c) * 4096 + h * 512 + vv0 + vq];
            Bs[c][vq + 0] = bv.x; Bs[c][vq + 1] = bv.y;
            Bs[c][vq + 2] = bv.z; Bs[c][vq + 3] = bv.w;
        }
        __syncthreads();
#pragma unroll
        for (int kk = 0; kk < 16; ++kk) {
            float4 ra = *(const float4*)&As[kk][ty * 4];
            float4 b0 = *(const float4*)&Bs[kk][tx * 8];
            float4 b1 = *(const float4*)&Bs[kk][tx * 8 + 4];
            float a4[4] = {ra.x, ra.y, ra.z, ra.w};
            float b8[8] = {b0.x, b0.y, b0.z, b0.w, b1.x, b1.y, b1.z, b1.w};
#pragma unroll
            for (int i = 0; i < 4; ++i)
#pragma unroll
                for (int j = 0; j < 8; ++j) acc[i][j] = fmaf(a4[i], b8[j], acc[i][j]);
        }
        __syncthreads();
    }
#pragma unroll
    for (int i = 0; i < 4; ++i) {
        size_t base = ((size_t)unit * 256 + d0 + ty * 4 + i) * 512 + vv0 + tx * 8;
        *(float4*)&d_U[base]     = make_float4(acc[i][0], acc[i][1], acc[i][2], acc[i][3]);
        *(float4*)&d_U[base + 4] = make_float4(acc[i][4], acc[i][5], acc[i][6], acc[i][7]);
    }
}

// ---------------- Phase B: in-place decay scan U_n -> S_n --------------------
__global__ void scan_kernel()
{
    int bh = blockIdx.x >> 9;
    int e = ((blockIdx.x & 511) << 8) + threadIdx.x;
    int h = bh & 7;
    float logb = logf(1.0f - exp2f(-5.0f - (float)h));
    float cd = expf(logb * 64.0f);
    size_t base = (size_t)bh * (32u * 131072u) + e;
    float p = 0.f;
#pragma unroll
    for (int n = 0; n < 32; ++n) {
        size_t idx = base + (size_t)n * 131072;
        float u = d_U[idx];
        d_U[idx] = p;
        p = p * cd + u;
    }
}

// ---------------- scores: Dmask ∘ (Q @ K^T) ----------------------------------
__global__ __launch_bounds__(256)
void scores_kernel()
{
    __shared__ float Qs[32][68];
    __shared__ float Ks[32][68];
    const int unit = blockIdx.x;
    const int bh = unit >> 5, n = unit & 31;
    const int b = bh >> 3, h = bh & 7;
    const int bt0 = b * TT + n * 64;
    const float logb = logf(1.0f - exp2f(-5.0f - (float)h));
    const int tid = threadIdx.x, tx = tid & 15, ty = tid >> 4;

    float acc[4][4];
#pragma unroll
    for (int i = 0; i < 4; ++i)
#pragma unroll
        for (int j = 0; j < 4; ++j) acc[i][j] = 0.f;

    for (int k0 = 0; k0 < 256; k0 += 32) {
#pragma unroll
        for (int l = 0; l < 2; ++l) {
            int idx = tid + l * 256;
            int row = idx >> 3;
            int kq = (idx & 7) * 4;
            float4 qv = *(const float4*)&d_q[(size_t)(bt0 + row) * 2048 + h * 256 + k0 + kq];
            Qs[kq + 0][row] = qv.x; Qs[kq + 1][row] = qv.y;
            Qs[kq + 2][row] = qv.z; Qs[kq + 3][row] = qv.w;
            float4 kv = *(const float4*)&d_k[(size_t)(bt0 + row) * 2048 + h * 256 + k0 + kq];
            Ks[kq + 0][row] = kv.x; Ks[kq + 1][row] = kv.y;
            Ks[kq + 2][row] = kv.z; Ks[kq + 3][row] = kv.w;
        }
        __syncthreads();
#pragma unroll
        for (int kk = 0; kk < 32; ++kk) {
            float4 ra = *(const float4*)&Qs[kk][ty * 4];
            float4 rb = *(const float4*)&Ks[kk][tx * 4];
            float a4[4] = {ra.x, ra.y, ra.z, ra.w};
            float b4[4] = {rb.x, rb.y, rb.z, rb.w};
#pragma unroll
            for (int i = 0; i < 4; ++i)
#pragma unroll
                for (int j = 0; j < 4; ++j) acc[i][j] = fmaf(a4[i], b4[j], acc[i][j]);
        }
        __syncthreads();
    }
#pragma unroll
    for (int ii = 0; ii < 4; ++ii)
#pragma unroll
        for (int jj = 0; jj < 4; ++jj) {
            int i = ty * 4 + ii, j = tx * 4 + jj, m = i - j;
            float val = (m >= 0) ? acc[ii][jj] * expf(logb * (float)m) : 0.f;
            d_sc[((size_t)unit * 64 + i) * 64 + j] = val;
        }
}

// ---------------- Phase C: o = (q∘q_dec)@S_n + scores@V ----------------------
__global__ __launch_bounds__(256)
void chunk_out_kernel()
{
    __shared__ float As[16][68];
    __shared__ float Bs[16][132];
    const int tid = threadIdx.x;
    const int vv0 = blockIdx.x * 128;
    const int unit = blockIdx.y;
    const int bh = unit >> 5, n = unit & 31;
    const int b = bh >> 3, h = bh & 7;
    const int bt0 = b * TT + n * 64;
    const float logb = logf(1.0f - exp2f(-5.0f - (float)h));
    const int tx = tid & 15, ty = tid >> 4;

    float acc[4][8];
#pragma unroll
    for (int i = 0; i < 4; ++i)
#pragma unroll
        for (int j = 0; j < 8; ++j) acc[i][j] = 0.f;

    for (int s = 0; s < 20; ++s) {
        const int k0 = s * 16;
        {
            int ar = tid >> 2, kq = (tid & 3) * 4;
            float4 a;
            if (k0 < 256) {
                a = *(const float4*)&d_q[(size_t)(bt0 + ar) * 2048 + h * 256 + k0 + kq];
                float qd = expf(logb * (float)(ar + 1));
                a.x *= qd; a.y *= qd; a.z *= qd; a.w *= qd;
            } else {
                a = *(const float4*)&d_sc[((size_t)unit * 64 + ar) * 64 + (k0 - 256) + kq];
            }
            As[kq + 0][ar] = a.x; As[kq + 1][ar] = a.y;
            As[kq + 2][ar] = a.z; As[kq + 3][ar] = a.w;
        }
#pragma unroll
        for (int l = 0; l < 2; ++l) {
            int idx = tid + l * 256;
            int c = idx >> 5, vq = (idx & 31) * 4;
            float4 bv;
            if (k0 < 256)
                bv = *(const float4*)&d_U[((size_t)unit * 256 + k0 + c) * 512 + vv0 + vq];
            else
                bv = *(const float4*)&d_v[(size_t)(bt0 + (k0 - 256) + c) * 4096 + h * 512 + vv0 + vq];
            Bs[c][vq + 0] = bv.x; Bs[c][vq + 1] = bv.y;
            Bs[c][vq + 2] = bv.z; Bs[c][vq + 3] = bv.w;
        }
        __syncthreads();
#pragma unroll
        for (int kk = 0; kk < 16; ++kk) {
            float4 ra = *(const float4*)&As[kk][ty * 4];
            float4 b0 = *(const float4*)&Bs[kk][tx * 8];
            float4 b1 = *(const float4*)&Bs[kk][tx * 8 + 4];
            float a4[4] = {ra.x, ra.y, ra.z, ra.w};
            float b8[8] = {b0.x, b0.y, b0.z, b0.w, b1.x, b1.y, b1.z, b1.w};
#pragma unroll
            for (int i = 0; i < 4; ++i)
#pragma unroll
                for (int j = 0; j < 8; ++j) acc[i][j] = fmaf(a4[i], b8[j], acc[i][j]);
        }
        __syncthreads();
    }
#pragma unroll
    for (int i = 0; i < 4; ++i) {
        size_t base = (size_t)(bt0 + ty * 4 + i) * 4096 + h * 512 + vv0 + tx * 8;
        *(float4*)&d_o[base]     = make_float4(acc[i][0], acc[i][1], acc[i][2], acc[i][3]);
        *(float4*)&d_o[base + 4] = make_float4(acc[i][4], acc[i][5], acc[i][6], acc[i][7]);
    }
}

// ------- rmsnorm + silu gating, emits bf16 hi/lo directly for the out GEMM ---
__global__ void gate_norm_kernel(const float* __restrict__ gw)
{
    __shared__ float red[4];
    const int row = blockIdx.x;
    const int bt = row >> 3, h = row & 7;
    const size_t base = (size_t)bt * 4096 + h * 512;
    const int tid = threadIdx.x;

    float4 ov = *(const float4*)&d_o[base + tid * 4];
    float ss = ov.x * ov.x + ov.y * ov.y + ov.z * ov.z + ov.w * ov.w;
#pragma unroll
    for (int off = 16; off; off >>= 1) ss += __shfl_xor_sync(0xffffffffu, ss, off);
    if ((tid & 31) == 0) red[tid >> 5] = ss;
    __syncthreads();
    float tot = red[0] + red[1] + red[2] + red[3];
    float inv = rsqrtf(tot * (1.0f / 512.0f) + 1e-5f);

    float4 gv = *(const float4*)&d_g[base + tid * 4];
    float4 w  = *(const float4*)&gw[tid * 4];
    float o0 = ov.x * inv * w.x * (gv.x / (1.f + expf(-gv.x)));
    float o1 = ov.y * inv * w.y * (gv.y / (1.f + expf(-gv.y)));
    float o2 = ov.z * inv * w.z * (gv.z / (1.f + expf(-gv.z)));
    float o3 = ov.w * inv * w.w * (gv.w / (1.f + expf(-gv.w)));

    size_t e = base + tid * 4;
    __nv_bfloat16 h0 = __float2bfloat16(o0), h1 = __float2bfloat16(o1);
    __nv_bfloat16 h2 = __float2bfloat16(o2), h3 = __float2bfloat16(o3);
    *(__nv_bfloat162*)&sO_h[e]     = __halves2bfloat162(h0, h1);
    *(__nv_bfloat162*)&sO_h[e + 2] = __halves2bfloat162(h2, h3);
    *(__nv_bfloat162*)&sO_l[e]     = __halves2bfloat162(__float2bfloat16(o0 - __bfloat162float(h0)),
                                                        __float2bfloat16(o1 - __bfloat162float(h1)));
    *(__nv_bfloat162*)&sO_l[e + 2] = __halves2bfloat162(__float2bfloat16(o2 - __bfloat162float(h2)),
                                                        __float2bfloat16(o3 - __bfloat162float(h3)));
}

// ---------------- launch ------------------------------------------------------
extern "C" void kernel_launch(void* const* d_in, const int* in_sizes, int n_in,
                              void* d_out, int out_size)
{
    const float* X  = (const float*)d_in[0];
    const float* Wq = (const float*)d_in[1];
    const float* Wk = (const float*)d_in[2];
    const float* Wv = (const float*)d_in[3];
    const float* Wg = (const float*)d_in[4];
    const float* Wo = (const float*)d_in[5];
    const float* gw = (const float*)d_in[6];
    float* out = (float*)d_out;

    float *q, *k, *v, *g;
    cudaGetSymbolAddress((void**)&q, d_q);
    cudaGetSymbolAddress((void**)&k, d_k);
    cudaGetSymbolAddress((void**)&v, d_v);
    cudaGetSymbolAddress((void**)&g, d_g);

    __nv_bfloat16 *xh, *xl, *wqh, *wql, *wkh, *wkl, *wvh, *wvl, *wgh, *wgl, *woh, *wol, *oh, *ol;
    cudaGetSymbolAddress((void**)&xh, sX_h);   cudaGetSymbolAddress((void**)&xl, sX_l);
    cudaGetSymbolAddress((void**)&wqh, sWq_h); cudaGetSymbolAddress((void**)&wql, sWq_l);
    cudaGetSymbolAddress((void**)&wkh, sWk_h); cudaGetSymbolAddress((void**)&wkl, sWk_l);
    cudaGetSymbolAddress((void**)&wvh, sWv_h); cudaGetSymbolAddress((void**)&wvl, sWv_l);
    cudaGetSymbolAddress((void**)&wgh, sWg_h); cudaGetSymbolAddress((void**)&wgl, sWg_l);
    cudaGetSymbolAddress((void**)&woh, sWo_h); cudaGetSymbolAddress((void**)&wol, sWo_l);
    cudaGetSymbolAddress((void**)&oh, sO_h);   cudaGetSymbolAddress((void**)&ol, sO_l);

    rope_table_kernel<<<1024, 256>>>();

    // one-time splits
    split_kernel<<<8192, 256>>>(X,  xh,  xl,  2097152);
    split_kernel<<<4096, 256>>>(Wq, wqh, wql, 1048576);
    split_kernel<<<4096, 256>>>(Wk, wkh, wkl, 1048576);
    split_kernel<<<8192, 256>>>(Wv, wvh, wvl, 2097152);
    split_kernel<<<8192, 256>>>(Wg, wgh, wgl, 2097152);
    split_kernel<<<8192, 256>>>(Wo, woh, wol, 2097152);

    // Projections on tensor cores (virtual-K bf16)
    gemm_bf16v<<<dim3(16, 32), 256>>>(xh, xl, wqh, wql, q, 4096, 2048, 2048);
    gemm_bf16v<<<dim3(16, 32), 256>>>(xh, xl, wkh, wkl, k, 4096, 2048, 2048);
    gemm_bf16v<<<dim3(32, 32), 256>>>(xh, xl, wvh, wvl, v, 4096, 4096, 2048);
    gemm_bf16v<<<dim3(32, 32), 256>>>(xh, xl, wgh, wgl, g, 4096, 4096, 2048);

    rope_kernel<<<16384, 256>>>();

    chunk_kv_kernel<<<dim3(16, 512), 256>>>();
    scan_kernel<<<8192, 256>>>();
    scores_kernel<<<512, 256>>>();
    chunk_out_kernel<<<dim3(4, 512), 256>>>();

    gate_norm_kernel<<<32768, 128>>>(gw);

    gemm_bf16v<<<dim3(16, 32), 256>>>(oh, ol, woh, wol, out, 4096, 2048, 4096);
}

// round 8
// speedup vs baseline: 1.8940x; 1.0378x over previous
#include <cuda_runtime.h>
#include <cuda_bf16.h>
#include <math.h>
#include <stdint.h>

// Problem constants: B=2, T=2048, D=2048, H=8, DK=256, DV=512, C=64, N=32
#define TT 2048

// ---------------- scratch (static device memory; no allocs allowed) ----------
__device__ float d_q[(size_t)4096 * 2048];
__device__ float d_k[(size_t)4096 * 2048];
__device__ float d_v[(size_t)4096 * 4096];
__device__ float d_g[(size_t)4096 * 4096];
__device__ float d_o[(size_t)4096 * 4096];
__device__ float d_U[(size_t)512 * 256 * 512]; // per-chunk KV -> prefix states (in place)
__device__ float d_sc[(size_t)512 * 64 * 64];  // decayed attention scores
__device__ float d_ropec[2048 * 128];
__device__ float d_ropes[2048 * 128];

// bf16 hi/lo split operands for tensor-core GEMMs
__device__ __nv_bfloat16 sX_h[(size_t)4096 * 2048],  sX_l[(size_t)4096 * 2048];
__device__ __nv_bfloat16 sWq_h[(size_t)2048 * 2048], sWq_l[(size_t)2048 * 2048];
__device__ __nv_bfloat16 sWk_h[(size_t)2048 * 2048], sWk_l[(size_t)2048 * 2048];
__device__ __nv_bfloat16 sWv_h[(size_t)4096 * 2048], sWv_l[(size_t)4096 * 2048];
__device__ __nv_bfloat16 sWg_h[(size_t)4096 * 2048], sWg_l[(size_t)4096 * 2048];
__device__ __nv_bfloat16 sWo_h[(size_t)2048 * 4096], sWo_l[(size_t)2048 * 4096];
__device__ __nv_bfloat16 sO_h[(size_t)4096 * 4096],  sO_l[(size_t)4096 * 4096];

// ---------------- fp32 -> bf16 hi/lo split (one-time per operand) ------------
__global__ void split_kernel(const float* __restrict__ src,
                             __nv_bfloat16* __restrict__ hi,
                             __nv_bfloat16* __restrict__ lo, int n4)
{
    int i = blockIdx.x * blockDim.x + threadIdx.x;
    if (i >= n4) return;
    float4 v = ((const float4*)src)[i];
    __nv_bfloat16 hx = __float2bfloat16(v.x), hy = __float2bfloat16(v.y);
    __nv_bfloat16 hz = __float2bfloat16(v.z), hw = __float2bfloat16(v.w);
    __nv_bfloat162 h0 = __halves2bfloat162(hx, hy), h1 = __halves2bfloat162(hz, hw);
    __nv_bfloat162 l0 = __halves2bfloat162(__float2bfloat16(v.x - __bfloat162float(hx)),
                                           __float2bfloat16(v.y - __bfloat162float(hy)));
    __nv_bfloat162 l1 = __halves2bfloat162(__float2bfloat16(v.z - __bfloat162float(hz)),
                                           __float2bfloat16(v.w - __bfloat162float(hw)));
    ((__nv_bfloat162*)hi)[i * 2]     = h0;
    ((__nv_bfloat162*)hi)[i * 2 + 1] = h1;
    ((__nv_bfloat162*)lo)[i * 2]     = l0;
    ((__nv_bfloat162*)lo)[i * 2 + 1] = l1;
}

// =====================================================================
// bf16 tensor-core GEMM over virtual K' = 3K:
//   seg0: Ah*Bh   seg1: Al*Bh   seg2: Ah*Bl   =>  C ~= A*B^T (fp32, ll dropped)
// Block 128x128, K-step 32, 8 warps of 64x32, 2-stage cp.async pipeline,
// 2 blocks/SM (128-reg budget) so barrier/wait stalls are covered cross-block.
// =====================================================================
#define GSTRIDE 40   // bf16 elems per smem row (32 + 8 pad) -> 80B, LDSM conflict-free

__device__ __forceinline__ void ldsm_x4(uint32_t& r0, uint32_t& r1, uint32_t& r2, uint32_t& r3, uint32_t addr) {
    asm volatile("ldmatrix.sync.aligned.m8n8.x4.shared.b16 {%0,%1,%2,%3}, [%4];\n"
                 : "=r"(r0), "=r"(r1), "=r"(r2), "=r"(r3) : "r"(addr));
}
__device__ __forceinline__ void mma16816(float* c, const uint32_t* a, const uint32_t* b) {
    asm volatile("mma.sync.aligned.m16n8k16.row.col.f32.bf16.bf16.f32 "
                 "{%0,%1,%2,%3},{%4,%5,%6,%7},{%8,%9},{%0,%1,%2,%3};\n"
                 : "+f"(c[0]), "+f"(c[1]), "+f"(c[2]), "+f"(c[3])
                 : "r"(a[0]), "r"(a[1]), "r"(a[2]), "r"(a[3]), "r"(b[0]), "r"(b[1]));
}
__device__ __forceinline__ void cp16(uint32_t dst, const void* src) {
    asm volatile("cp.async.cg.shared.global [%0], [%1], 16;\n" :: "r"(dst), "l"(src));
}

__global__ __launch_bounds__(256, 2)
void gemm_bf16v(const __nv_bfloat16* __restrict__ Ah, const __nv_bfloat16* __restrict__ Al,
                const __nv_bfloat16* __restrict__ Bh, const __nv_bfloat16* __restrict__ Bl,
                float* __restrict__ C, int M, int N, int K)
{
    __shared__ __nv_bfloat16 SA[2][128 * GSTRIDE];
    __shared__ __nv_bfloat16 SB[2][128 * GSTRIDE];

    const int tid = threadIdx.x;
    const int warp = tid >> 5, lane = tid & 31;
    const int wm = warp >> 2, wn = warp & 3;
    const int bm = blockIdx.y * 128, bn = blockIdx.x * 128;

    const int kseg = K >> 5;          // k-steps per segment
    const int nk = 3 * kseg;          // virtual k-steps

    const uint32_t sa0 = (uint32_t)__cvta_generic_to_shared(&SA[0][0]);
    const uint32_t sb0 = (uint32_t)__cvta_generic_to_shared(&SB[0][0]);
    const uint32_t stage_bytes = 128 * GSTRIDE * 2;

    // producer addressing: 512 16B-chunks per tile, 2 per thread
    const int p_row = tid >> 2;             // 0..63 (x2 via l)
    const int p_ch  = (tid & 3) << 3;       // bf16 elem offset 0,8,16,24

    float acc[4][4][4];
#pragma unroll
    for (int i = 0; i < 4; ++i)
#pragma unroll
        for (int j = 0; j < 4; ++j)
#pragma unroll
            for (int e = 0; e < 4; ++e) acc[i][j][e] = 0.f;

    const int a_r = (lane & 15), a_c8 = ((lane >> 4) << 3);
    const int b_r = ((lane >> 4) << 3) + (lane & 7), b_c8 = (((lane >> 3) & 1) << 3);

    auto issue = [&](int ks) {
        int seg = (ks >= kseg) + (ks >= 2 * kseg);       // no integer div
        const __nv_bfloat16* Asel = (seg == 1) ? Al : Ah;
        const __nv_bfloat16* Bsel = (seg == 2) ? Bl : Bh;
        int k0 = (ks - seg * kseg) << 5;
        int s = ks & 1;
#pragma unroll
        for (int l = 0; l < 2; ++l) {
            int row = p_row + l * 64;
            uint32_t soff = (uint32_t)(row * GSTRIDE + p_ch) * 2 + s * stage_bytes;
            cp16(sa0 + soff, Asel + (size_t)(bm + row) * K + k0 + p_ch);
            cp16(sb0 + soff, Bsel + (size_t)(bn + row) * K + k0 + p_ch);
        }
        asm volatile("cp.async.commit_group;\n");
    };

    issue(0);
    for (int ks = 0; ks < nk; ++ks) {
        if (ks + 1 < nk) {
            issue(ks + 1);
            asm volatile("cp.async.wait_group 1;\n");
        } else {
            asm volatile("cp.async.wait_group 0;\n");
        }
        __syncthreads();

        const int s = ks & 1;
        const uint32_t sa = sa0 + s * stage_bytes;
        const uint32_t sb = sb0 + s * stage_bytes;
#pragma unroll
        for (int kh = 0; kh < 2; ++kh) {
            uint32_t af[4][4], bf[4][2];
#pragma unroll
            for (int mt = 0; mt < 4; ++mt) {
                int off = ((wm * 64 + mt * 16 + a_r) * GSTRIDE + kh * 16 + a_c8) * 2;
                ldsm_x4(af[mt][0], af[mt][1], af[mt][2], af[mt][3], sa + off);
            }
#pragma unroll
            for (int p = 0; p < 2; ++p) {
                int off = ((wn * 32 + p * 16 + b_r) * GSTRIDE + kh * 16 + b_c8) * 2;
                ldsm_x4(bf[2 * p][0], bf[2 * p][1], bf[2 * p + 1][0], bf[2 * p + 1][1], sb + off);
            }
#pragma unroll
            for (int mt = 0; mt < 4; ++mt)
#pragma unroll
                for (int nt = 0; nt < 4; ++nt)
                    mma16816(acc[mt][nt], af[mt], bf[nt]);
        }
        __syncthreads();
    }

    // epilogue (float4 stores: d0,d1 + neighbor-lane pairs are contiguous per row)
#pragma unroll
    for (int mt = 0; mt < 4; ++mt)
#pragma unroll
        for (int nt = 0; nt < 4; ++nt) {
            int row = bm + wm * 64 + mt * 16 + (lane >> 2);
            int col = bn + wn * 32 + nt * 8 + (lane & 3) * 2;
            *(float2*)(C + (size_t)row * N + col)       = make_float2(acc[mt][nt][0], acc[mt][nt][1]);
            *(float2*)(C + (size_t)(row + 8) * N + col) = make_float2(acc[mt][nt][2], acc[mt][nt][3]);
        }
}

// ---------------- RoPE table (accurate fp64 trig, once per launch) -----------
__global__ void rope_table_kernel()
{
    int idx = blockIdx.x * blockDim.x + threadIdx.x;   // < 2048*128
    int i = idx & 127, t = idx >> 7;
    double invf_d = exp(-(double)i * (9.210340371976184 / 128.0));
    float phase = (float)t * (float)invf_d;            // replicate reference f32 rounding
    double sd, cd;
    sincos((double)phase, &sd, &cd);
    d_ropec[idx] = (float)cd;
    d_ropes[idx] = (float)sd;
}

// ---------------- RoPE on q and k (q also scaled by 1/16) --------------------
__global__ void rope_kernel()
{
    int idx = blockIdx.x * blockDim.x + threadIdx.x;   // < 4096*8*128
    int i = idx & 127;
    int h = (idx >> 7) & 7;
    int bt = idx >> 10;
    int t = bt & (TT - 1);
    float c = d_ropec[(t << 7) + i], s = d_ropes[(t << 7) + i];

    size_t base = (size_t)bt * 2048 + h * 256 + i;
    float x1 = d_q[base], x2 = d_q[base + 128];
    d_q[base]       = (x1 * c - x2 * s) * 0.0625f;
    d_q[base + 128] = (x2 * c + x1 * s) * 0.0625f;
    x1 = d_k[base]; x2 = d_k[base + 128];
    d_k[base]       = x1 * c - x2 * s;
    d_k[base + 128] = x2 * c + x1 * s;
}

// ---------------- Phase A: U[unit] = (k ∘ k_dec)^T @ v  ----------------------
__global__ __launch_bounds__(256)
void chunk_kv_kernel()
{
    __shared__ float As[16][68];
    __shared__ float Bs[16][132];
    const int tid = threadIdx.x;
    const int tile = blockIdx.x;           // 16 tiles: 4 d x 4 vv
    const int unit = blockIdx.y;           // 512
    const int d0 = (tile >> 2) * 64;
    const int vv0 = (tile & 3) * 128;
    const int bh = unit >> 5, n = unit & 31;
    const int b = bh >> 3, h = bh & 7;
    const int bt0 = b * TT + n * 64;
    const float logb = logf(1.0f - exp2f(-5.0f - (float)h));
    const int tx = tid & 15, ty = tid >> 4;

    float acc[4][8];
#pragma unroll
    for (int i = 0; i < 4; ++i)
#pragma unroll
        for (int j = 0; j < 8; ++j) acc[i][j] = 0.f;

    for (int c0 = 0; c0 < 64; c0 += 16) {
        {
            int c = tid >> 4, dq = (tid & 15) * 4;
            float4 a = *(const float4*)&d_k[(size_t)(bt0 + c0 + c) * 2048 + h * 256 + d0 + dq];
            float kd = expf(logb * (float)(63 - (c0 + c)));
            As[c][dq + 0] = a.x * kd; As[c][dq + 1] = a.y * kd;
            As[c][dq + 2] = a.z * kd; As[c][dq + 3] = a.w * kd;
        }
#pragma unroll
        for (int l = 0; l < 2; ++l) {
            int idx = tid + l * 256;
            int c = idx >> 5, vq = (idx & 31) * 4;
            float4 bv = *(const float4*)&d_v[(size_t)(bt0 + c0 + c) * 4096 + h * 512 + vv0 + vq];
            Bs[c][vq + 0] = bv.x; Bs[c][vq + 1] = bv.y;
            Bs[c][vq + 2] = bv.z; Bs[c][vq + 3] = bv.w;
        }
        __syncthreads();
#pragma unroll
        for (int kk = 0; kk < 16; ++kk) {
            float4 ra = *(const float4*)&As[kk][ty * 4];
            float4 b0 = *(const float4*)&Bs[kk][tx * 8];
            float4 b1 = *(const float4*)&Bs[kk][tx * 8 + 4];
            float a4[4] = {ra.x, ra.y, ra.z, ra.w};
            float b8[8] = {b0.x, b0.y, b0.z, b0.w, b1.x, b1.y, b1.z, b1.w};
#pragma unroll
            for (int i = 0; i < 4; ++i)
#pragma unroll
                for (int j = 0; j < 8; ++j) acc[i][j] = fmaf(a4[i], b8[j], acc[i][j]);
        }
        __syncthreads();
    }
#pragma unroll
    for (int i = 0; i < 4; ++i) {
        size_t base = ((size_t)unit * 256 + d0 + ty * 4 + i) * 512 + vv0 + tx * 8;
        *(float4*)&d_U[base]     = make_float4(acc[i][0], acc[i][1], acc[i][2], acc[i][3]);
        *(float4*)&d_U[base + 4] = make_float4(acc[i][4], acc[i][5], acc[i][6], acc[i][7]);
    }
}

// ---------------- Phase B: in-place decay scan U_n -> S_n --------------------
__global__ void scan_kernel()
{
    int bh = blockIdx.x >> 9;
    int e = ((blockIdx.x & 511) << 8) + threadIdx.x;
    int h = bh & 7;
    float logb = logf(1.0f - exp2f(-5.0f - (float)h));
    float cd = expf(logb * 64.0f);
    size_t base = (size_t)bh * (32u * 131072u) + e;
    float p = 0.f;
#pragma unroll
    for (int n = 0; n < 32; ++n) {
        size_t idx = base + (size_t)n * 131072;
        float u = d_U[idx];
        d_U[idx] = p;
        p = p * cd + u;
    }
}

// ---------------- scores: Dmask ∘ (Q @ K^T) ----------------------------------
__global__ __launch_bounds__(256)
void scores_kernel()
{
    __shared__ float Qs[32][68];
    __shared__ float Ks[32][68];
    const int unit = blockIdx.x;
    const int bh = unit >> 5, n = unit & 31;
    const int b = bh >> 3, h = bh & 7;
    const int bt0 = b * TT + n * 64;
    const float logb = logf(1.0f - exp2f(-5.0f - (float)h));
    const int tid = threadIdx.x, tx = tid & 15, ty = tid >> 4;

    float acc[4][4];
#pragma unroll
    for (int i = 0; i < 4; ++i)
#pragma unroll
        for (int j = 0; j < 4; ++j) acc[i][j] = 0.f;

    for (int k0 = 0; k0 < 256; k0 += 32) {
#pragma unroll
        for (int l = 0; l < 2; ++l) {
            int idx = tid + l * 256;
            int row = idx >> 3;
            int kq = (idx & 7) * 4;
            float4 qv = *(const float4*)&d_q[(size_t)(bt0 + row) * 2048 + h * 256 + k0 + kq];
            Qs[kq + 0][row] = qv.x; Qs[kq + 1][row] = qv.y;
            Qs[kq + 2][row] = qv.z; Qs[kq + 3][row] = qv.w;
            float4 kv = *(const float4*)&d_k[(size_t)(bt0 + row) * 2048 + h * 256 + k0 + kq];
            Ks[kq + 0][row] = kv.x; Ks[kq + 1][row] = kv.y;
            Ks[kq + 2][row] = kv.z; Ks[kq + 3][row] = kv.w;
        }
        __syncthreads();
#pragma unroll
        for (int kk = 0; kk < 32; ++kk) {
            float4 ra = *(const float4*)&Qs[kk][ty * 4];
            float4 rb = *(const float4*)&Ks[kk][tx * 4];
            float a4[4] = {ra.x, ra.y, ra.z, ra.w};
            float b4[4] = {rb.x, rb.y, rb.z, rb.w};
#pragma unroll
            for (int i = 0; i < 4; ++i)
#pragma unroll
                for (int j = 0; j < 4; ++j) acc[i][j] = fmaf(a4[i], b4[j], acc[i][j]);
        }
        __syncthreads();
    }
#pragma unroll
    for (int ii = 0; ii < 4; ++ii)
#pragma unroll
        for (int jj = 0; jj < 4; ++jj) {
            int i = ty * 4 + ii, j = tx * 4 + jj, m = i - j;
            float val = (m >= 0) ? acc[ii][jj] * expf(logb * (float)m) : 0.f;
            d_sc[((size_t)unit * 64 + i) * 64 + j] = val;
        }
}

// ---------------- Phase C: o = (q∘q_dec)@S_n + scores@V ----------------------
__global__ __launch_bounds__(256)
void chunk_out_kernel()
{
    __shared__ float As[16][68];
    __shared__ float Bs[16][132];
    const int tid = threadIdx.x;
    const int vv0 = blockIdx.x * 128;
    const int unit = blockIdx.y;
    const int bh = unit >> 5, n = unit & 31;
    const int b = bh >> 3, h = bh & 7;
    const int bt0 = b * TT + n * 64;
    const float logb = logf(1.0f - exp2f(-5.0f - (float)h));
    const int tx = tid & 15, ty = tid >> 4;

    float acc[4][8];
#pragma unroll
    for (int i = 0; i < 4; ++i)
#pragma unroll
        for (int j = 0; j < 8; ++j) acc[i][j] = 0.f;

    for (int s = 0; s < 20; ++s) {
        const int k0 = s * 16;
        {
            int ar = tid >> 2, kq = (tid & 3) * 4;
            float4 a;
            if (k0 < 256) {
                a = *(const float4*)&d_q[(size_t)(bt0 + ar) * 2048 + h * 256 + k0 + kq];
                float qd = expf(logb * (float)(ar + 1));
                a.x *= qd; a.y *= qd; a.z *= qd; a.w *= qd;
            } else {
                a = *(const float4*)&d_sc[((size_t)unit * 64 + ar) * 64 + (k0 - 256) + kq];
            }
            As[kq + 0][ar] = a.x; As[kq + 1][ar] = a.y;
            As[kq + 2][ar] = a.z; As[kq + 3][ar] = a.w;
        }
#pragma unroll
        for (int l = 0; l < 2; ++l) {
            int idx = tid + l * 256;
            int c = idx >> 5, vq = (idx & 31) * 4;
            float4 bv;
            if (k0 < 256)
                bv = *(const float4*)&d_U[((size_t)unit * 256 + k0 + c) * 512 + vv0 + vq];
            else
                bv = *(const float4*)&d_v[(size_t)(bt0 + (k0 - 256) + c) * 4096 + h * 512 + vv0 + vq];
            Bs[c][vq + 0] = bv.x; Bs[c][vq + 1] = bv.y;
            Bs[c][vq + 2] = bv.z; Bs[c][vq + 3] = bv.w;
        }
        __syncthreads();
#pragma unroll
        for (int kk = 0; kk < 16; ++kk) {
            float4 ra = *(const float4*)&As[kk][ty * 4];
            float4 b0 = *(const float4*)&Bs[kk][tx * 8];
            float4 b1 = *(const float4*)&Bs[kk][tx * 8 + 4];
            float a4[4] = {ra.x, ra.y, ra.z, ra.w};
            float b8[8] = {b0.x, b0.y, b0.z, b0.w, b1.x, b1.y, b1.z, b1.w};
#pragma unroll
            for (int i = 0; i < 4; ++i)
#pragma unroll
                for (int j = 0; j < 8; ++j) acc[i][j] = fmaf(a4[i], b8[j], acc[i][j]);
        }
        __syncthreads();
    }
#pragma unroll
    for (int i = 0; i < 4; ++i) {
        size_t base = (size_t)(bt0 + ty * 4 + i) * 4096 + h * 512 + vv0 + tx * 8;
        *(float4*)&d_o[base]     = make_float4(acc[i][0], acc[i][1], acc[i][2], acc[i][3]);
        *(float4*)&d_o[base + 4] = make_float4(acc[i][4], acc[i][5], acc[i][6], acc[i][7]);
    }
}

// ------- rmsnorm + silu gating, emits bf16 hi/lo directly for the out GEMM ---
__global__ void gate_norm_kernel(const float* __restrict__ gw)
{
    __shared__ float red[4];
    const int row = blockIdx.x;
    const int bt = row >> 3, h = row & 7;
    const size_t base = (size_t)bt * 4096 + h * 512;
    const int tid = threadIdx.x;

    float4 ov = *(const float4*)&d_o[base + tid * 4];
    float ss = ov.x * ov.x + ov.y * ov.y + ov.z * ov.z + ov.w * ov.w;
#pragma unroll
    for (int off = 16; off; off >>= 1) ss += __shfl_xor_sync(0xffffffffu, ss, off);
    if ((tid & 31) == 0) red[tid >> 5] = ss;
    __syncthreads();
    float tot = red[0] + red[1] + red[2] + red[3];
    float inv = rsqrtf(tot * (1.0f / 512.0f) + 1e-5f);

    float4 gv = *(const float4*)&d_g[base + tid * 4];
    float4 w  = *(const float4*)&gw[tid * 4];
    float o0 = ov.x * inv * w.x * (gv.x / (1.f + expf(-gv.x)));
    float o1 = ov.y * inv * w.y * (gv.y / (1.f + expf(-gv.y)));
    float o2 = ov.z * inv * w.z * (gv.z / (1.f + expf(-gv.z)));
    float o3 = ov.w * inv * w.w * (gv.w / (1.f + expf(-gv.w)));

    size_t e = base + tid * 4;
    __nv_bfloat16 h0 = __float2bfloat16(o0), h1 = __float2bfloat16(o1);
    __nv_bfloat16 h2 = __float2bfloat16(o2), h3 = __float2bfloat16(o3);
    *(__nv_bfloat162*)&sO_h[e]     = __halves2bfloat162(h0, h1);
    *(__nv_bfloat162*)&sO_h[e + 2] = __halves2bfloat162(h2, h3);
    *(__nv_bfloat162*)&sO_l[e]     = __halves2bfloat162(__float2bfloat16(o0 - __bfloat162float(h0)),
                                                        __float2bfloat16(o1 - __bfloat162float(h1)));
    *(__nv_bfloat162*)&sO_l[e + 2] = __halves2bfloat162(__float2bfloat16(o2 - __bfloat162float(h2)),
                                                        __float2bfloat16(o3 - __bfloat162float(h3)));
}

// ---------------- launch ------------------------------------------------------
extern "C" void kernel_launch(void* const* d_in, const int* in_sizes, int n_in,
                              void* d_out, int out_size)
{
    const float* X  = (const float*)d_in[0];
    const float* Wq = (const float*)d_in[1];
    const float* Wk = (const float*)d_in[2];
    const float* Wv = (const float*)d_in[3];
    const float* Wg = (const float*)d_in[4];
    const float* Wo = (const float*)d_in[5];
    const float* gw = (const float*)d_in[6];
    float* out = (float*)d_out;

    float *q, *k, *v, *g;
    cudaGetSymbolAddress((void**)&q, d_q);
    cudaGetSymbolAddress((void**)&k, d_k);
    cudaGetSymbolAddress((void**)&v, d_v);
    cudaGetSymbolAddress((void**)&g, d_g);

    __nv_bfloat16 *xh, *xl, *wqh, *wql, *wkh, *wkl, *wvh, *wvl, *wgh, *wgl, *woh, *wol, *oh, *ol;
    cudaGetSymbolAddress((void**)&xh, sX_h);   cudaGetSymbolAddress((void**)&xl, sX_l);
    cudaGetSymbolAddress((void**)&wqh, sWq_h); cudaGetSymbolAddress((void**)&wql, sWq_l);
    cudaGetSymbolAddress((void**)&wkh, sWk_h); cudaGetSymbolAddress((void**)&wkl, sWk_l);
    cudaGetSymbolAddress((void**)&wvh, sWv_h); cudaGetSymbolAddress((void**)&wvl, sWv_l);
    cudaGetSymbolAddress((void**)&wgh, sWg_h); cudaGetSymbolAddress((void**)&wgl, sWg_l);
    cudaGetSymbolAddress((void**)&woh, sWo_h); cudaGetSymbolAddress((void**)&wol, sWo_l);
    cudaGetSymbolAddress((void**)&oh, sO_h);   cudaGetSymbolAddress((void**)&ol, sO_l);

    rope_table_kernel<<<1024, 256>>>();

    // one-time splits
    split_kernel<<<8192, 256>>>(X,  xh,  xl,  2097152);
    split_kernel<<<4096, 256>>>(Wq, wqh, wql, 1048576);
    split_kernel<<<4096, 256>>>(Wk, wkh, wkl, 1048576);
    split_kernel<<<8192, 256>>>(Wv, wvh, wvl, 2097152);
    split_kernel<<<8192, 256>>>(Wg, wgh, wgl, 2097152);
    split_kernel<<<8192, 256>>>(Wo, woh, wol, 2097152);

    // Projections on tensor cores (virtual-K bf16)
    gemm_bf16v<<<dim3(16, 32), 256>>>(xh, xl, wqh, wql, q, 4096, 2048, 2048);
    gemm_bf16v<<<dim3(16, 32), 256>>>(xh, xl, wkh, wkl, k, 4096, 2048, 2048);
    gemm_bf16v<<<dim3(32, 32), 256>>>(xh, xl, wvh, wvl, v, 4096, 4096, 2048);
    gemm_bf16v<<<dim3(32, 32), 256>>>(xh, xl, wgh, wgl, g, 4096, 4096, 2048);

    rope_kernel<<<16384, 256>>>();

    chunk_kv_kernel<<<dim3(16, 512), 256>>>();
    scan_kernel<<<8192, 256>>>();
    scores_kernel<<<512, 256>>>();
    chunk_out_kernel<<<dim3(4, 512), 256>>>();

    gate_norm_kernel<<<32768, 128>>>(gw);

    gemm_bf16v<<<dim3(16, 32), 256>>>(oh, ol, woh, wol, out, 4096, 2048, 4096);
}

// round 10
// speedup vs baseline: 2.1302x; 1.1247x over previous
#include <cuda_runtime.h>
#include <cuda_bf16.h>
#include <math.h>
#include <stdint.h>

// Problem constants: B=2, T=2048, D=2048, H=8, DK=256, DV=512, C=64, N=32
#define TT 2048

// ---------------- scratch (static device memory; no allocs allowed) ----------
__device__ float d_q[(size_t)4096 * 2048];
__device__ float d_k[(size_t)4096 * 2048];
__device__ float d_v[(size_t)4096 * 4096];
__device__ float d_g[(size_t)4096 * 4096];
__device__ float d_o[(size_t)4096 * 4096];
__device__ float d_U[(size_t)512 * 256 * 512]; // per-chunk KV (fp32, phase A out)
__device__ float d_ropec[2048 * 128];
__device__ float d_ropes[2048 * 128];

// bf16 hi/lo split operands for tensor-core GEMMs
__device__ __nv_bfloat16 sX_h[(size_t)4096 * 2048],  sX_l[(size_t)4096 * 2048];
__device__ __nv_bfloat16 sWq_h[(size_t)2048 * 2048], sWq_l[(size_t)2048 * 2048];
__device__ __nv_bfloat16 sWk_h[(size_t)2048 * 2048], sWk_l[(size_t)2048 * 2048];
__device__ __nv_bfloat16 sWv_h[(size_t)4096 * 2048], sWv_l[(size_t)4096 * 2048];
__device__ __nv_bfloat16 sWg_h[(size_t)4096 * 2048], sWg_l[(size_t)4096 * 2048];
__device__ __nv_bfloat16 sWo_h[(size_t)2048 * 4096], sWo_l[(size_t)2048 * 4096];
__device__ __nv_bfloat16 sO_h[(size_t)4096 * 4096],  sO_l[(size_t)4096 * 4096];

// phase operands (hi/lo)
__device__ __nv_bfloat16 sQh[(size_t)4096 * 2048],  sQl[(size_t)4096 * 2048];   // q post-rope, /16
__device__ __nv_bfloat16 sKdh[(size_t)4096 * 2048], sKdl[(size_t)4096 * 2048];  // k*k_dec
__device__ __nv_bfloat16 sVh[(size_t)4096 * 4096],  sVl[(size_t)4096 * 4096];
__device__ __nv_bfloat16 sUh[(size_t)512 * 256 * 512], sUl[(size_t)512 * 256 * 512]; // prefix states
__device__ __nv_bfloat16 sSch[(size_t)512 * 64 * 64], sScl[(size_t)512 * 64 * 64];   // decayed scores

// ---------------- fp32 -> bf16 hi/lo split (one-time per operand) ------------
__global__ void split_kernel(const float* __restrict__ src,
                             __nv_bfloat16* __restrict__ hi,
                             __nv_bfloat16* __restrict__ lo, int n4)
{
    int i = blockIdx.x * blockDim.x + threadIdx.x;
    if (i >= n4) return;
    float4 v = ((const float4*)src)[i];
    __nv_bfloat16 hx = __float2bfloat16(v.x), hy = __float2bfloat16(v.y);
    __nv_bfloat16 hz = __float2bfloat16(v.z), hw = __float2bfloat16(v.w);
    ((__nv_bfloat162*)hi)[i * 2]     = __halves2bfloat162(hx, hy);
    ((__nv_bfloat162*)hi)[i * 2 + 1] = __halves2bfloat162(hz, hw);
    ((__nv_bfloat162*)lo)[i * 2]     = __halves2bfloat162(
        __float2bfloat16(v.x - __bfloat162float(hx)), __float2bfloat16(v.y - __bfloat162float(hy)));
    ((__nv_bfloat162*)lo)[i * 2 + 1] = __halves2bfloat162(
        __float2bfloat16(v.z - __bfloat162float(hz)), __float2bfloat16(v.w - __bfloat162float(hw)));
}

// ---------------- mma/ldsm/cp.async primitives --------------------------------
__device__ __forceinline__ void ldsm_x4(uint32_t& r0, uint32_t& r1, uint32_t& r2, uint32_t& r3, uint32_t addr) {
    asm volatile("ldmatrix.sync.aligned.m8n8.x4.shared.b16 {%0,%1,%2,%3}, [%4];\n"
                 : "=r"(r0), "=r"(r1), "=r"(r2), "=r"(r3) : "r"(addr));
}
__device__ __forceinline__ void ldsm_x4t(uint32_t& r0, uint32_t& r1, uint32_t& r2, uint32_t& r3, uint32_t addr) {
    asm volatile("ldmatrix.sync.aligned.m8n8.x4.trans.shared.b16 {%0,%1,%2,%3}, [%4];\n"
                 : "=r"(r0), "=r"(r1), "=r"(r2), "=r"(r3) : "r"(addr));
}
__device__ __forceinline__ void mma16816(float* c, const uint32_t* a, const uint32_t* b) {
    asm volatile("mma.sync.aligned.m16n8k16.row.col.f32.bf16.bf16.f32 "
                 "{%0,%1,%2,%3},{%4,%5,%6,%7},{%8,%9},{%0,%1,%2,%3};\n"
                 : "+f"(c[0]), "+f"(c[1]), "+f"(c[2]), "+f"(c[3])
                 : "r"(a[0]), "r"(a[1]), "r"(a[2]), "r"(a[3]), "r"(b[0]), "r"(b[1]));
}
__device__ __forceinline__ void cp16(uint32_t dst, const void* src) {
    asm volatile("cp.async.cg.shared.global [%0], [%1], 16;\n" :: "r"(dst), "l"(src));
}

// =====================================================================
// Projection GEMM (R8): C[M,N] = A[M,K]*B[N,K]^T over virtual K'=3K.
// =====================================================================
#define GSTRIDE 40

__global__ __launch_bounds__(256, 2)
void gemm_bf16v(const __nv_bfloat16* __restrict__ Ah, const __nv_bfloat16* __restrict__ Al,
                const __nv_bfloat16* __restrict__ Bh, const __nv_bfloat16* __restrict__ Bl,
                float* __restrict__ C, int M, int N, int K)
{
    __shared__ __nv_bfloat16 SA[2][128 * GSTRIDE];
    __shared__ __nv_bfloat16 SB[2][128 * GSTRIDE];

    const int tid = threadIdx.x;
    const int warp = tid >> 5, lane = tid & 31;
    const int wm = warp >> 2, wn = warp & 3;
    const int bm = blockIdx.y * 128, bn = blockIdx.x * 128;
    const int kseg = K >> 5, nk = 3 * kseg;

    const uint32_t sa0 = (uint32_t)__cvta_generic_to_shared(&SA[0][0]);
    const uint32_t sb0 = (uint32_t)__cvta_generic_to_shared(&SB[0][0]);
    const uint32_t stage_bytes = 128 * GSTRIDE * 2;
    const int p_row = tid >> 2, p_ch = (tid & 3) << 3;

    float acc[4][4][4];
#pragma unroll
    for (int i = 0; i < 4; ++i)
#pragma unroll
        for (int j = 0; j < 4; ++j)
#pragma unroll
            for (int e = 0; e < 4; ++e) acc[i][j][e] = 0.f;

    const int a_r = (lane & 15), a_c8 = ((lane >> 4) << 3);
    const int b_r = ((lane >> 4) << 3) + (lane & 7), b_c8 = (((lane >> 3) & 1) << 3);

    auto issue = [&](int ks) {
        int seg = (ks >= kseg) + (ks >= 2 * kseg);
        const __nv_bfloat16* Asel = (seg == 1) ? Al : Ah;
        const __nv_bfloat16* Bsel = (seg == 2) ? Bl : Bh;
        int k0 = (ks - seg * kseg) << 5;
        int s = ks & 1;
#pragma unroll
        for (int l = 0; l < 2; ++l) {
            int row = p_row + l * 64;
            uint32_t soff = (uint32_t)(row * GSTRIDE + p_ch) * 2 + s * stage_bytes;
            cp16(sa0 + soff, Asel + (size_t)(bm + row) * K + k0 + p_ch);
            cp16(sb0 + soff, Bsel + (size_t)(bn + row) * K + k0 + p_ch);
        }
        asm volatile("cp.async.commit_group;\n");
    };

    issue(0);
    for (int ks = 0; ks < nk; ++ks) {
        if (ks + 1 < nk) {
            issue(ks + 1);
            asm volatile("cp.async.wait_group 1;\n");
        } else {
            asm volatile("cp.async.wait_group 0;\n");
        }
        __syncthreads();
        const int s = ks & 1;
        const uint32_t sa = sa0 + s * stage_bytes, sb = sb0 + s * stage_bytes;
#pragma unroll
        for (int kh = 0; kh < 2; ++kh) {
            uint32_t af[4][4], bf[4][2];
#pragma unroll
            for (int mt = 0; mt < 4; ++mt) {
                int off = ((wm * 64 + mt * 16 + a_r) * GSTRIDE + kh * 16 + a_c8) * 2;
                ldsm_x4(af[mt][0], af[mt][1], af[mt][2], af[mt][3], sa + off);
            }
#pragma unroll
            for (int p = 0; p < 2; ++p) {
                int off = ((wn * 32 + p * 16 + b_r) * GSTRIDE + kh * 16 + b_c8) * 2;
                ldsm_x4(bf[2 * p][0], bf[2 * p][1], bf[2 * p + 1][0], bf[2 * p + 1][1], sb + off);
            }
#pragma unroll
            for (int mt = 0; mt < 4; ++mt)
#pragma unroll
                for (int nt = 0; nt < 4; ++nt)
                    mma16816(acc[mt][nt], af[mt], bf[nt]);
        }
        __syncthreads();
    }
#pragma unroll
    for (int mt = 0; mt < 4; ++mt)
#pragma unroll
        for (int nt = 0; nt < 4; ++nt) {
            int row = bm + wm * 64 + mt * 16 + (lane >> 2);
            int col = bn + wn * 32 + nt * 8 + (lane & 3) * 2;
            *(float2*)(C + (size_t)row * N + col)       = make_float2(acc[mt][nt][0], acc[mt][nt][1]);
            *(float2*)(C + (size_t)(row + 8) * N + col) = make_float2(acc[mt][nt][2], acc[mt][nt][3]);
        }
}

// ---------------- RoPE table -------------------------------------------------
__global__ void rope_table_kernel()
{
    int idx = blockIdx.x * blockDim.x + threadIdx.x;
    int i = idx & 127, t = idx >> 7;
    double invf_d = exp(-(double)i * (9.210340371976184 / 128.0));
    float phase = (float)t * (float)invf_d;
    double sd, cd;
    sincos((double)phase, &sd, &cd);
    d_ropec[idx] = (float)cd;
    d_ropes[idx] = (float)sd;
}

__device__ __forceinline__ void split_store(__nv_bfloat16* hi, __nv_bfloat16* lo, size_t i, float x) {
    __nv_bfloat16 h = __float2bfloat16(x);
    hi[i] = h;
    lo[i] = __float2bfloat16(x - __bfloat162float(h));
}

// ---------------- RoPE: q (scaled 1/16) and k; emit fp32 + hi/lo -------------
__global__ void rope_kernel()
{
    int idx = blockIdx.x * blockDim.x + threadIdx.x;   // < 4096*8*128
    int i = idx & 127;
    int h = (idx >> 7) & 7;
    int bt = idx >> 10;
    int t = bt & (TT - 1);
    float c = d_ropec[(t << 7) + i], s = d_ropes[(t << 7) + i];

    size_t base = (size_t)bt * 2048 + h * 256 + i;
    float x1 = d_q[base], x2 = d_q[base + 128];
    float q1 = (x1 * c - x2 * s) * 0.0625f;
    float q2 = (x2 * c + x1 * s) * 0.0625f;
    d_q[base] = q1; d_q[base + 128] = q2;
    split_store(sQh, sQl, base, q1);
    split_store(sQh, sQl, base + 128, q2);

    x1 = d_k[base]; x2 = d_k[base + 128];
    float k1 = x1 * c - x2 * s;
    float k2 = x2 * c + x1 * s;
    d_k[base] = k1; d_k[base + 128] = k2;

    float logb = logf(1.0f - exp2f(-5.0f - (float)h));
    float kd = expf(logb * (float)(63 - (t & 63)));
    split_store(sKdh, sKdl, base, k1 * kd);
    split_store(sKdh, sKdl, base + 128, k2 * kd);
}

// =====================================================================
// Phase A (tensor): U[unit] = (k∘k_dec)^T @ v, 3-pass split-bf16.
// Block: 128(d) x 128(vv), contraction c=64 loaded whole; 8 warps 64x32.
// A via trans-ldsm of kd[c,d] tiles; B via trans-ldsm of v[c,vv] tiles.
// =====================================================================
#define KVS 136    // smem row stride (bf16); 272B == 4 words mod 32 -> conflict-free
extern __shared__ __nv_bfloat16 kvsm[];

__global__ void chunk_kv_tc()
{
    const int tid = threadIdx.x;
    const int warp = tid >> 5, lane = tid & 31;
    const int wm = warp >> 2, wn = warp & 3;
    const int d0 = (blockIdx.x >> 2) * 128, vv0 = (blockIdx.x & 3) * 128;
    const int unit = blockIdx.y;
    const int bh = unit >> 5, n = unit & 31;
    const int b = bh >> 3, h = bh & 7;
    const int bt0 = b * TT + n * 64;
    const uint32_t sb = (uint32_t)__cvta_generic_to_shared(kvsm);
    const uint32_t AH = 0, AL = 64 * KVS, BH = 2 * 64 * KVS, BL = 3 * 64 * KVS;

    // single-shot fill: 4 tiles x 64 rows x 16 chunks
#pragma unroll
    for (int l = 0; l < 16; ++l) {
        int idx = tid + l * 256;
        int t = idx >> 10, r = (idx >> 4) & 63, ch = idx & 15;
        const __nv_bfloat16* src;
        if (t == 0)      src = sKdh + (size_t)(bt0 + r) * 2048 + h * 256 + d0 + ch * 8;
        else if (t == 1) src = sKdl + (size_t)(bt0 + r) * 2048 + h * 256 + d0 + ch * 8;
        else if (t == 2) src = sVh  + (size_t)(bt0 + r) * 4096 + h * 512 + vv0 + ch * 8;
        else             src = sVl  + (size_t)(bt0 + r) * 4096 + h * 512 + vv0 + ch * 8;
        cp16(sb + (uint32_t)(t * 64 * KVS + r * KVS + ch * 8) * 2, src);
    }
    asm volatile("cp.async.commit_group;\ncp.async.wait_group 0;\n");
    __syncthreads();

    float acc[4][4][4];
#pragma unroll
    for (int i = 0; i < 4; ++i)
#pragma unroll
        for (int j = 0; j < 4; ++j)
#pragma unroll
            for (int e = 0; e < 4; ++e) acc[i][j][e] = 0.f;

    // trans-A addressing (A = kd^T): lanes -> (c-row, d-colgroup)
    const int tra_r = (lane & 7) + (((lane >> 4) & 1) << 3);
    const int tra_c = ((lane >> 3) & 1) << 3;
    // trans-B addressing (B = v^T): lanes -> (c-row, vv-colgroup)
    const int trb_r = lane & 15;
    const int trb_c = (lane >> 4) << 3;

#pragma unroll
    for (int p = 0; p < 3; ++p) {
        const uint32_t Ab = (p == 1) ? AL : AH;
        const uint32_t Bb = (p == 2) ? BL : BH;
#pragma unroll
        for (int cb = 0; cb < 4; ++cb) {
            const int c16 = cb * 16;
            uint32_t af[4][4], bf[4][2];
#pragma unroll
            for (int mt = 0; mt < 4; ++mt) {
                uint32_t off = (Ab + (uint32_t)(c16 + tra_r) * KVS + wm * 64 + mt * 16 + tra_c) * 2;
                ldsm_x4t(af[mt][0], af[mt][1], af[mt][2], af[mt][3], sb + off);
            }
#pragma unroll
            for (int g = 0; g < 2; ++g) {
                uint32_t off = (Bb + (uint32_t)(c16 + trb_r) * KVS + wn * 32 + g * 16 + trb_c) * 2;
                ldsm_x4t(bf[2 * g][0], bf[2 * g][1], bf[2 * g + 1][0], bf[2 * g + 1][1], sb + off);
            }
#pragma unroll
            for (int mt = 0; mt < 4; ++mt)
#pragma unroll
                for (int nt = 0; nt < 4; ++nt)
                    mma16816(acc[mt][nt], af[mt], bf[nt]);
        }
    }

#pragma unroll
    for (int mt = 0; mt < 4; ++mt)
#pragma unroll
        for (int nt = 0; nt < 4; ++nt) {
            int row = d0 + wm * 64 + mt * 16 + (lane >> 2);
            int col = vv0 + wn * 32 + nt * 8 + (lane & 3) * 2;
            size_t p0 = ((size_t)unit * 256 + row) * 512 + col;
            *(float2*)&d_U[p0]                 = make_float2(acc[mt][nt][0], acc[mt][nt][1]);
            *(float2*)&d_U[p0 + (size_t)8*512] = make_float2(acc[mt][nt][2], acc[mt][nt][3]);
        }
}

// ---------------- Phase B: decay scan U_n -> prefix states (emit hi/lo) ------
__global__ void scan_kernel()
{
    int bh = blockIdx.x >> 9;
    int e = ((blockIdx.x & 511) << 8) + threadIdx.x;
    int h = bh & 7;
    float logb = logf(1.0f - exp2f(-5.0f - (float)h));
    float cd = expf(logb * 64.0f);
    size_t base = (size_t)bh * (32u * 131072u) + e;
    float p = 0.f;
#pragma unroll
    for (int n = 0; n < 32; ++n) {
        size_t idx = base + (size_t)n * 131072;
        float u = d_U[idx];
        __nv_bfloat16 hp = __float2bfloat16(p);
        sUh[idx] = hp;
        sUl[idx] = __float2bfloat16(p - __bfloat162float(hp));
        p = p * cd + u;
    }
}

// ---------------- scores: Dmask ∘ (Q @ K^T), emits hi/lo ---------------------
__global__ __launch_bounds__(256)
void scores_kernel()
{
    __shared__ float Qs[32][68];
    __shared__ float Ks[32][68];
    const int unit = blockIdx.x;
    const int bh = unit >> 5, n = unit & 31;
    const int b = bh >> 3, h = bh & 7;
    const int bt0 = b * TT + n * 64;
    const float logb = logf(1.0f - exp2f(-5.0f - (float)h));
    const int tid = threadIdx.x, tx = tid & 15, ty = tid >> 4;

    float acc[4][4];
#pragma unroll
    for (int i = 0; i < 4; ++i)
#pragma unroll
        for (int j = 0; j < 4; ++j) acc[i][j] = 0.f;

    for (int k0 = 0; k0 < 256; k0 += 32) {
#pragma unroll
        for (int l = 0; l < 2; ++l) {
            int idx = tid + l * 256;
            int row = idx >> 3;
            int kq = (idx & 7) * 4;
            float4 qv = *(const float4*)&d_q[(size_t)(bt0 + row) * 2048 + h * 256 + k0 + kq];
            Qs[kq + 0][row] = qv.x; Qs[kq + 1][row] = qv.y;
            Qs[kq + 2][row] = qv.z; Qs[kq + 3][row] = qv.w;
            float4 kv = *(const float4*)&d_k[(size_t)(bt0 + row) * 2048 + h * 256 + k0 + kq];
            Ks[kq + 0][row] = kv.x; Ks[kq + 1][row] = kv.y;
            Ks[kq + 2][row] = kv.z; Ks[kq + 3][row] = kv.w;
        }
        __syncthreads();
#pragma unroll
        for (int kk = 0; kk < 32; ++kk) {
            float4 ra = *(const float4*)&Qs[kk][ty * 4];
            float4 rb = *(const float4*)&Ks[kk][tx * 4];
            float a4[4] = {ra.x, ra.y, ra.z, ra.w};
            float b4[4] = {rb.x, rb.y, rb.z, rb.w};
#pragma unroll
            for (int i = 0; i < 4; ++i)
#pragma unroll
                for (int j = 0; j < 4; ++j) acc[i][j] = fmaf(a4[i], b4[j], acc[i][j]);
        }
        __syncthreads();
    }
#pragma unroll
    for (int ii = 0; ii < 4; ++ii)
#pragma unroll
        for (int jj = 0; jj < 4; ++jj) {
            int i = ty * 4 + ii, j = tx * 4 + jj, m = i - j;
            float val = (m >= 0) ? acc[ii][jj] * expf(logb * (float)m) : 0.f;
            split_store(sSch, sScl, (size_t)unit * 4096 + i * 64 + j, val);
        }
}

// =====================================================================
// Phase C (tensor): o = (q∘q_dec)@S_n + scores@V.
// Block 64(m) x 256(vv), 8 warps 32x64, double-buffered cp.async.
// 30 k-steps: 24 of q·S (3 passes x 256) then scale by q_dec, 6 of sc·V.
// A non-trans (q rows / sc rows); B trans (S[d,vv], v[c,vv]).
// =====================================================================
#define COA 40                    // A smem stride (elems)
#define COB 264                   // B smem stride (elems); 528B == 4 words mod 32

__global__ __launch_bounds__(256)
void chunk_out_tc()
{
    __shared__ __nv_bfloat16 Asm[2 * 64 * COA];
    __shared__ __nv_bfloat16 Bsm[2 * 32 * COB];
    const int tid = threadIdx.x;
    const int warp = tid >> 5, lane = tid & 31;
    const int wm = warp >> 2, wn = warp & 3;     // 2 x 4 warps: 32 x 64 tiles
    const int vv0 = blockIdx.x * 256;
    const int unit = blockIdx.y;
    const int bh = unit >> 5, n = unit & 31;
    const int b = bh >> 3, h = bh & 7;
    const int bt0 = b * TT + n * 64;
    const float logb = logf(1.0f - exp2f(-5.0f - (float)h));
    const uint32_t a0u = (uint32_t)__cvta_generic_to_shared(Asm);
    const uint32_t b0u = (uint32_t)__cvta_generic_to_shared(Bsm);

    float acc[2][8][4];
#pragma unroll
    for (int i = 0; i < 2; ++i)
#pragma unroll
        for (int j = 0; j < 8; ++j)
#pragma unroll
            for (int e = 0; e < 4; ++e) acc[i][j][e] = 0.f;

    auto issue = [&](int j) {
        const __nv_bfloat16 *Ap, *Bp;
        int Astr, Bstr;
        if (j < 24) {
            int p = j >> 3, kk = (j & 7) * 32;
            Ap = ((p == 1) ? sQl : sQh) + (size_t)bt0 * 2048 + h * 256 + kk;  Astr = 2048;
            Bp = ((p == 2) ? sUl : sUh) + ((size_t)unit * 256 + kk) * 512 + vv0; Bstr = 512;
        } else {
            int j2 = j - 24, p = j2 >> 1, kk = (j2 & 1) * 32;
            Ap = ((p == 1) ? sScl : sSch) + (size_t)unit * 4096 + kk;  Astr = 64;
            Bp = ((p == 2) ? sVl : sVh) + (size_t)(bt0 + kk) * 4096 + h * 512 + vv0; Bstr = 4096;
        }
        int s = j & 1;
        { // A: 64 rows x 4 chunks, 1/thread
            int r = tid >> 2, ch = tid & 3;
            cp16(a0u + (uint32_t)(s * 64 * COA + r * COA + ch * 8) * 2, Ap + (size_t)r * Astr + ch * 8);
        }
#pragma unroll
        for (int l = 0; l < 4; ++l) { // B: 32 rows x 32 chunks, 4/thread
            int idx = tid + l * 256;
            int r = idx >> 5, ch = idx & 31;
            cp16(b0u + (uint32_t)(s * 32 * COB + r * COB + ch * 8) * 2, Bp + (size_t)r * Bstr + ch * 8);
        }
        asm volatile("cp.async.commit_group;\n");
    };

    const int a_r = lane & 15, a_c8 = (lane >> 4) << 3;  // non-trans A
    const int tb_r = lane & 15, tb_c8 = (lane >> 4) << 3; // trans B

    issue(0);
    for (int i = 0; i < 30; ++i) {
        if (i + 1 < 30) {
            issue(i + 1);
            asm volatile("cp.async.wait_group 1;\n");
        } else {
            asm volatile("cp.async.wait_group 0;\n");
        }
        __syncthreads();
        const int s = i & 1;
        const uint32_t ab = a0u + (uint32_t)(s * 64 * COA) * 2;
        const uint32_t bb = b0u + (uint32_t)(s * 32 * COB) * 2;
#pragma unroll
        for (int kh = 0; kh < 2; ++kh) {
            uint32_t af[2][4], bf[8][2];
#pragma unroll
            for (int mt = 0; mt < 2; ++mt) {
                uint32_t off = ((uint32_t)(wm * 32 + mt * 16 + a_r) * COA + kh * 16 + a_c8) * 2;
                ldsm_x4(af[mt][0], af[mt][1], af[mt][2], af[mt][3], ab + off);
            }
#pragma unroll
            for (int ng = 0; ng < 4; ++ng) {
                uint32_t off = ((uint32_t)(kh * 16 + tb_r) * COB + wn * 64 + ng * 16 + tb_c8) * 2;
                ldsm_x4t(bf[2 * ng][0], bf[2 * ng][1], bf[2 * ng + 1][0], bf[2 * ng + 1][1], bb + off);
            }
#pragma unroll
            for (int mt = 0; mt < 2; ++mt)
#pragma unroll
                for (int nt = 0; nt < 8; ++nt)
                    mma16816(acc[mt][nt], af[mt], bf[nt]);
        }
        __syncthreads();
        if (i == 23) { // end of q·S passes: scale by q_dec(row)
#pragma unroll
            for (int mt = 0; mt < 2; ++mt) {
                float r0 = (float)(wm * 32 + mt * 16 + (lane >> 2));
                float qd0 = expf(logb * (r0 + 1.0f));
                float qd1 = expf(logb * (r0 + 9.0f));
#pragma unroll
                for (int nt = 0; nt < 8; ++nt) {
                    acc[mt][nt][0] *= qd0; acc[mt][nt][1] *= qd0;
                    acc[mt][nt][2] *= qd1; acc[mt][nt][3] *= qd1;
                }
            }
        }
    }

#pragma unroll
    for (int mt = 0; mt < 2; ++mt)
#pragma unroll
        for (int nt = 0; nt < 8; ++nt) {
            int row = bt0 + wm * 32 + mt * 16 + (lane >> 2);
            int col = h * 512 + vv0 + wn * 64 + nt * 8 + (lane & 3) * 2;
            *(float2*)&d_o[(size_t)row * 4096 + col]       = make_float2(acc[mt][nt][0], acc[mt][nt][1]);
            *(float2*)&d_o[(size_t)(row + 8) * 4096 + col] = make_float2(acc[mt][nt][2], acc[mt][nt][3]);
        }
}

// ------- rmsnorm + silu gating, emits bf16 hi/lo directly for the out GEMM ---
__global__ void gate_norm_kernel(const float* __restrict__ gw)
{
    __shared__ float red[4];
    const int row = blockIdx.x;
    const int bt = row >> 3, h = row & 7;
    const size_t base = (size_t)bt * 4096 + h * 512;
    const int tid = threadIdx.x;

    float4 ov = *(const float4*)&d_o[base + tid * 4];
    float ss = ov.x * ov.x + ov.y * ov.y + ov.z * ov.z + ov.w * ov.w;
#pragma unroll
    for (int off = 16; off; off >>= 1) ss += __shfl_xor_sync(0xffffffffu, ss, off);
    if ((tid & 31) == 0) red[tid >> 5] = ss;
    __syncthreads();
    float tot = red[0] + red[1] + red[2] + red[3];
    float inv = rsqrtf(tot * (1.0f / 512.0f) + 1e-5f);

    float4 gv = *(const float4*)&d_g[base + tid * 4];
    float4 w  = *(const float4*)&gw[tid * 4];
    float o0 = ov.x * inv * w.x * (gv.x / (1.f + expf(-gv.x)));
    float o1 = ov.y * inv * w.y * (gv.y / (1.f + expf(-gv.y)));
    float o2 = ov.z * inv * w.z * (gv.z / (1.f + expf(-gv.z)));
    float o3 = ov.w * inv * w.w * (gv.w / (1.f + expf(-gv.w)));

    size_t e = base + tid * 4;
    split_store(sO_h, sO_l, e + 0, o0);
    split_store(sO_h, sO_l, e + 1, o1);
    split_store(sO_h, sO_l, e + 2, o2);
    split_store(sO_h, sO_l, e + 3, o3);
}

// ---------------- launch ------------------------------------------------------
extern "C" void kernel_launch(void* const* d_in, const int* in_sizes, int n_in,
                              void* d_out, int out_size)
{
    const float* X  = (const float*)d_in[0];
    const float* Wq = (const float*)d_in[1];
    const float* Wk = (const float*)d_in[2];
    const float* Wv = (const float*)d_in[3];
    const float* Wg = (const float*)d_in[4];
    const float* Wo = (const float*)d_in[5];
    const float* gw = (const float*)d_in[6];
    float* out = (float*)d_out;

    float *q, *k, *v, *g;
    cudaGetSymbolAddress((void**)&q, d_q);
    cudaGetSymbolAddress((void**)&k, d_k);
    cudaGetSymbolAddress((void**)&v, d_v);
    cudaGetSymbolAddress((void**)&g, d_g);

    __nv_bfloat16 *xh, *xl, *wqh, *wql, *wkh, *wkl, *wvh, *wvl, *wgh, *wgl, *woh, *wol, *oh, *ol, *vh, *vl;
    cudaGetSymbolAddress((void**)&xh, sX_h);   cudaGetSymbolAddress((void**)&xl, sX_l);
    cudaGetSymbolAddress((void**)&wqh, sWq_h); cudaGetSymbolAddress((void**)&wql, sWq_l);
    cudaGetSymbolAddress((void**)&wkh, sWk_h); cudaGetSymbolAddress((void**)&wkl, sWk_l);
    cudaGetSymbolAddress((void**)&wvh, sWv_h); cudaGetSymbolAddress((void**)&wvl, sWv_l);
    cudaGetSymbolAddress((void**)&wgh, sWg_h); cudaGetSymbolAddress((void**)&wgl, sWg_l);
    cudaGetSymbolAddress((void**)&woh, sWo_h); cudaGetSymbolAddress((void**)&wol, sWo_l);
    cudaGetSymbolAddress((void**)&oh, sO_h);   cudaGetSymbolAddress((void**)&ol, sO_l);
    cudaGetSymbolAddress((void**)&vh, sVh);    cudaGetSymbolAddress((void**)&vl, sVl);

    cudaFuncSetAttribute(chunk_kv_tc, cudaFuncAttributeMaxDynamicSharedMemorySize, 4 * 64 * KVS * 2);

    rope_table_kernel<<<1024, 256>>>();

    // one-time splits
    split_kernel<<<8192, 256>>>(X,  xh,  xl,  2097152);
    split_kernel<<<4096, 256>>>(Wq, wqh, wql, 1048576);
    split_kernel<<<4096, 256>>>(Wk, wkh, wkl, 1048576);
    split_kernel<<<8192, 256>>>(Wv, wvh, wvl, 2097152);
    split_kernel<<<8192, 256>>>(Wg, wgh, wgl, 2097152);
    split_kernel<<<8192, 256>>>(Wo, woh, wol, 2097152);

    // Projections (split-bf16 mma.sync)
    gemm_bf16v<<<dim3(16, 32), 256>>>(xh, xl, wqh, wql, q, 4096, 2048, 2048);
    gemm_bf16v<<<dim3(16, 32), 256>>>(xh, xl, wkh, wkl, k, 4096, 2048, 2048);
    gemm_bf16v<<<dim3(32, 32), 256>>>(xh, xl, wvh, wvl, v, 4096, 4096, 2048);
    gemm_bf16v<<<dim3(32, 32), 256>>>(xh, xl, wgh, wgl, g, 4096, 4096, 2048);

    rope_kernel<<<16384, 256>>>();
    split_kernel<<<16384, 256>>>(v, vh, vl, 4194304);

    chunk_kv_tc<<<dim3(8, 512), 256, 4 * 64 * KVS * 2>>>();
    scan_kernel<<<8192, 256>>>();
    scores_kernel<<<512, 256>>>();
    chunk_out_tc<<<dim3(2, 512), 256>>>();

    gate_norm_kernel<<<32768, 128>>>(gw);

    gemm_bf16v<<<dim3(16, 32), 256>>>(oh, ol, woh, wol, out, 4096, 2048, 4096);
}

// round 11
// speedup vs baseline: 2.2359x; 1.0496x over previous
#include <cuda_runtime.h>
#include <cuda_bf16.h>
#include <math.h>
#include <stdint.h>

// Problem constants: B=2, T=2048, D=2048, H=8, DK=256, DV=512, C=64, N=32
#define TT 2048

// ---------------- scratch (static device memory; no allocs allowed) ----------
__device__ float d_q[(size_t)4096 * 2048];
__device__ float d_k[(size_t)4096 * 2048];
__device__ float d_v[(size_t)4096 * 4096];
__device__ float d_g[(size_t)4096 * 4096];
__device__ float d_o[(size_t)4096 * 4096];
__device__ float d_U[(size_t)512 * 256 * 512]; // per-chunk KV (fp32, phase A out)
__device__ float d_ropec[2048 * 128];
__device__ float d_ropes[2048 * 128];

// bf16 hi/lo split operands for tensor-core GEMMs
__device__ __nv_bfloat16 sX_h[(size_t)4096 * 2048],  sX_l[(size_t)4096 * 2048];
__device__ __nv_bfloat16 sWq_h[(size_t)2048 * 2048], sWq_l[(size_t)2048 * 2048];
__device__ __nv_bfloat16 sWk_h[(size_t)2048 * 2048], sWk_l[(size_t)2048 * 2048];
__device__ __nv_bfloat16 sWv_h[(size_t)4096 * 2048], sWv_l[(size_t)4096 * 2048];
__device__ __nv_bfloat16 sWg_h[(size_t)4096 * 2048], sWg_l[(size_t)4096 * 2048];
__device__ __nv_bfloat16 sWo_h[(size_t)2048 * 4096], sWo_l[(size_t)2048 * 4096];
__device__ __nv_bfloat16 sO_h[(size_t)4096 * 4096],  sO_l[(size_t)4096 * 4096];

// phase operands (hi/lo)
__device__ __nv_bfloat16 sQh[(size_t)4096 * 2048],  sQl[(size_t)4096 * 2048];   // q post-rope, /16
__device__ __nv_bfloat16 sKdh[(size_t)4096 * 2048], sKdl[(size_t)4096 * 2048];  // k*k_dec
__device__ __nv_bfloat16 sVh[(size_t)4096 * 4096],  sVl[(size_t)4096 * 4096];
__device__ __nv_bfloat16 sUh[(size_t)512 * 256 * 512], sUl[(size_t)512 * 256 * 512]; // prefix states
__device__ __nv_bfloat16 sSch[(size_t)512 * 64 * 64], sScl[(size_t)512 * 64 * 64];   // decayed scores

// ---------------- fp32 -> bf16 hi/lo split (one-time per operand) ------------
__global__ void split_kernel(const float* __restrict__ src,
                             __nv_bfloat16* __restrict__ hi,
                             __nv_bfloat16* __restrict__ lo, int n4)
{
    int i = blockIdx.x * blockDim.x + threadIdx.x;
    if (i >= n4) return;
    float4 v = ((const float4*)src)[i];
    __nv_bfloat16 hx = __float2bfloat16(v.x), hy = __float2bfloat16(v.y);
    __nv_bfloat16 hz = __float2bfloat16(v.z), hw = __float2bfloat16(v.w);
    ((__nv_bfloat162*)hi)[i * 2]     = __halves2bfloat162(hx, hy);
    ((__nv_bfloat162*)hi)[i * 2 + 1] = __halves2bfloat162(hz, hw);
    ((__nv_bfloat162*)lo)[i * 2]     = __halves2bfloat162(
        __float2bfloat16(v.x - __bfloat162float(hx)), __float2bfloat16(v.y - __bfloat162float(hy)));
    ((__nv_bfloat162*)lo)[i * 2 + 1] = __halves2bfloat162(
        __float2bfloat16(v.z - __bfloat162float(hz)), __float2bfloat16(v.w - __bfloat162float(hw)));
}

// ---------------- mma/ldsm/cp.async primitives --------------------------------
__device__ __forceinline__ void ldsm_x4(uint32_t& r0, uint32_t& r1, uint32_t& r2, uint32_t& r3, uint32_t addr) {
    asm volatile("ldmatrix.sync.aligned.m8n8.x4.shared.b16 {%0,%1,%2,%3}, [%4];\n"
                 : "=r"(r0), "=r"(r1), "=r"(r2), "=r"(r3) : "r"(addr));
}
__device__ __forceinline__ void ldsm_x4t(uint32_t& r0, uint32_t& r1, uint32_t& r2, uint32_t& r3, uint32_t addr) {
    asm volatile("ldmatrix.sync.aligned.m8n8.x4.trans.shared.b16 {%0,%1,%2,%3}, [%4];\n"
                 : "=r"(r0), "=r"(r1), "=r"(r2), "=r"(r3) : "r"(addr));
}
__device__ __forceinline__ void mma16816(float* c, const uint32_t* a, const uint32_t* b) {
    asm volatile("mma.sync.aligned.m16n8k16.row.col.f32.bf16.bf16.f32 "
                 "{%0,%1,%2,%3},{%4,%5,%6,%7},{%8,%9},{%0,%1,%2,%3};\n"
                 : "+f"(c[0]), "+f"(c[1]), "+f"(c[2]), "+f"(c[3])
                 : "r"(a[0]), "r"(a[1]), "r"(a[2]), "r"(a[3]), "r"(b[0]), "r"(b[1]));
}
__device__ __forceinline__ void cp16(uint32_t dst, const void* src) {
    asm volatile("cp.async.cg.shared.global [%0], [%1], 16;\n" :: "r"(dst), "l"(src));
}

// =====================================================================
// Projection GEMM: C[M,N] = A[M,K]*B[N,K]^T over virtual K'=3K.
// 3-stage cp.async ring, ONE barrier per k-step:
//   wait_group -> syncthreads -> issue(ks+2) -> compute(ks)
// (stage (ks+2)%3 aliases stage ks-1 whose readers passed this barrier).
// =====================================================================
#define GSTRIDE 40
#define PSTAGE_BYTES (128 * GSTRIDE * 2)      // 10240 B per operand tile
#define PSMEM (3 * 2 * PSTAGE_BYTES)          // 61440 B

extern __shared__ __nv_bfloat16 dynsm[];

__global__ __launch_bounds__(256, 2)
void gemm_bf16v(const __nv_bfloat16* __restrict__ Ah, const __nv_bfloat16* __restrict__ Al,
                const __nv_bfloat16* __restrict__ Bh, const __nv_bfloat16* __restrict__ Bl,
                float* __restrict__ C, int M, int N, int K)
{
    const int tid = threadIdx.x;
    const int warp = tid >> 5, lane = tid & 31;
    const int wm = warp >> 2, wn = warp & 3;
    const int bm = blockIdx.y * 128, bn = blockIdx.x * 128;
    const int kseg = K >> 5, nk = 3 * kseg;

    const uint32_t s0 = (uint32_t)__cvta_generic_to_shared(dynsm);
    const int p_row = tid >> 2, p_ch = (tid & 3) << 3;

    float acc[4][4][4];
#pragma unroll
    for (int i = 0; i < 4; ++i)
#pragma unroll
        for (int j = 0; j < 4; ++j)
#pragma unroll
            for (int e = 0; e < 4; ++e) acc[i][j][e] = 0.f;

    const int a_r = (lane & 15), a_c8 = ((lane >> 4) << 3);
    const int b_r = ((lane >> 4) << 3) + (lane & 7), b_c8 = (((lane >> 3) & 1) << 3);

    auto issue = [&](int ks) {
        int seg = (ks >= kseg) + (ks >= 2 * kseg);
        const __nv_bfloat16* Asel = (seg == 1) ? Al : Ah;
        const __nv_bfloat16* Bsel = (seg == 2) ? Bl : Bh;
        int k0 = (ks - seg * kseg) << 5;
        int s = ks % 3;
        uint32_t ab = s0 + (uint32_t)s * (2 * PSTAGE_BYTES);
#pragma unroll
        for (int l = 0; l < 2; ++l) {
            int row = p_row + l * 64;
            uint32_t soff = (uint32_t)(row * GSTRIDE + p_ch) * 2;
            cp16(ab + soff, Asel + (size_t)(bm + row) * K + k0 + p_ch);
            cp16(ab + PSTAGE_BYTES + soff, Bsel + (size_t)(bn + row) * K + k0 + p_ch);
        }
        asm volatile("cp.async.commit_group;\n");
    };

    issue(0);
    issue(1);
    for (int ks = 0; ks < nk; ++ks) {
        if (ks + 1 < nk)
            asm volatile("cp.async.wait_group 1;\n");
        else
            asm volatile("cp.async.wait_group 0;\n");
        __syncthreads();
        if (ks + 2 < nk) issue(ks + 2);

        const int s = ks % 3;
        const uint32_t sa = s0 + (uint32_t)s * (2 * PSTAGE_BYTES);
        const uint32_t sb = sa + PSTAGE_BYTES;
#pragma unroll
        for (int kh = 0; kh < 2; ++kh) {
            uint32_t af[4][4], bf[4][2];
#pragma unroll
            for (int mt = 0; mt < 4; ++mt) {
                int off = ((wm * 64 + mt * 16 + a_r) * GSTRIDE + kh * 16 + a_c8) * 2;
                ldsm_x4(af[mt][0], af[mt][1], af[mt][2], af[mt][3], sa + off);
            }
#pragma unroll
            for (int p = 0; p < 2; ++p) {
                int off = ((wn * 32 + p * 16 + b_r) * GSTRIDE + kh * 16 + b_c8) * 2;
                ldsm_x4(bf[2 * p][0], bf[2 * p][1], bf[2 * p + 1][0], bf[2 * p + 1][1], sb + off);
            }
#pragma unroll
            for (int mt = 0; mt < 4; ++mt)
#pragma unroll
                for (int nt = 0; nt < 4; ++nt)
                    mma16816(acc[mt][nt], af[mt], bf[nt]);
        }
    }

#pragma unroll
    for (int mt = 0; mt < 4; ++mt)
#pragma unroll
        for (int nt = 0; nt < 4; ++nt) {
            int row = bm + wm * 64 + mt * 16 + (lane >> 2);
            int col = bn + wn * 32 + nt * 8 + (lane & 3) * 2;
            *(float2*)(C + (size_t)row * N + col)       = make_float2(acc[mt][nt][0], acc[mt][nt][1]);
            *(float2*)(C + (size_t)(row + 8) * N + col) = make_float2(acc[mt][nt][2], acc[mt][nt][3]);
        }
}

// ---------------- RoPE table -------------------------------------------------
__global__ void rope_table_kernel()
{
    int idx = blockIdx.x * blockDim.x + threadIdx.x;
    int i = idx & 127, t = idx >> 7;
    double invf_d = exp(-(double)i * (9.210340371976184 / 128.0));
    float phase = (float)t * (float)invf_d;
    double sd, cd;
    sincos((double)phase, &sd, &cd);
    d_ropec[idx] = (float)cd;
    d_ropes[idx] = (float)sd;
}

__device__ __forceinline__ void split_store(__nv_bfloat16* hi, __nv_bfloat16* lo, size_t i, float x) {
    __nv_bfloat16 h = __float2bfloat16(x);
    hi[i] = h;
    lo[i] = __float2bfloat16(x - __bfloat162float(h));
}

// ---------------- RoPE: q (scaled 1/16) and k; emit fp32 + hi/lo -------------
__global__ void rope_kernel()
{
    int idx = blockIdx.x * blockDim.x + threadIdx.x;   // < 4096*8*128
    int i = idx & 127;
    int h = (idx >> 7) & 7;
    int bt = idx >> 10;
    int t = bt & (TT - 1);
    float c = d_ropec[(t << 7) + i], s = d_ropes[(t << 7) + i];

    size_t base = (size_t)bt * 2048 + h * 256 + i;
    float x1 = d_q[base], x2 = d_q[base + 128];
    float q1 = (x1 * c - x2 * s) * 0.0625f;
    float q2 = (x2 * c + x1 * s) * 0.0625f;
    d_q[base] = q1; d_q[base + 128] = q2;
    split_store(sQh, sQl, base, q1);
    split_store(sQh, sQl, base + 128, q2);

    x1 = d_k[base]; x2 = d_k[base + 128];
    float k1 = x1 * c - x2 * s;
    float k2 = x2 * c + x1 * s;
    d_k[base] = k1; d_k[base + 128] = k2;

    float logb = logf(1.0f - exp2f(-5.0f - (float)h));
    float kd = expf(logb * (float)(63 - (t & 63)));
    split_store(sKdh, sKdl, base, k1 * kd);
    split_store(sKdh, sKdl, base + 128, k2 * kd);
}

// =====================================================================
// Phase A (tensor): U[unit] = (k∘k_dec)^T @ v, 3-pass split-bf16.
// =====================================================================
#define KVS 136    // smem row stride (bf16); 272B == 4 words mod 32 -> conflict-free

__global__ void chunk_kv_tc()
{
    const int tid = threadIdx.x;
    const int warp = tid >> 5, lane = tid & 31;
    const int wm = warp >> 2, wn = warp & 3;
    const int d0 = (blockIdx.x >> 2) * 128, vv0 = (blockIdx.x & 3) * 128;
    const int unit = blockIdx.y;
    const int bh = unit >> 5, n = unit & 31;
    const int b = bh >> 3, h = bh & 7;
    const int bt0 = b * TT + n * 64;
    const uint32_t sb = (uint32_t)__cvta_generic_to_shared(dynsm);
    const uint32_t AH = 0, AL = 64 * KVS, BH = 2 * 64 * KVS, BL = 3 * 64 * KVS;

#pragma unroll
    for (int l = 0; l < 16; ++l) {
        int idx = tid + l * 256;
        int t = idx >> 10, r = (idx >> 4) & 63, ch = idx & 15;
        const __nv_bfloat16* src;
        if (t == 0)      src = sKdh + (size_t)(bt0 + r) * 2048 + h * 256 + d0 + ch * 8;
        else if (t == 1) src = sKdl + (size_t)(bt0 + r) * 2048 + h * 256 + d0 + ch * 8;
        else if (t == 2) src = sVh  + (size_t)(bt0 + r) * 4096 + h * 512 + vv0 + ch * 8;
        else             src = sVl  + (size_t)(bt0 + r) * 4096 + h * 512 + vv0 + ch * 8;
        cp16(sb + (uint32_t)(t * 64 * KVS + r * KVS + ch * 8) * 2, src);
    }
    asm volatile("cp.async.commit_group;\ncp.async.wait_group 0;\n");
    __syncthreads();

    float acc[4][4][4];
#pragma unroll
    for (int i = 0; i < 4; ++i)
#pragma unroll
        for (int j = 0; j < 4; ++j)
#pragma unroll
            for (int e = 0; e < 4; ++e) acc[i][j][e] = 0.f;

    const int tra_r = (lane & 7) + (((lane >> 4) & 1) << 3);
    const int tra_c = ((lane >> 3) & 1) << 3;
    const int trb_r = lane & 15;
    const int trb_c = (lane >> 4) << 3;

#pragma unroll
    for (int p = 0; p < 3; ++p) {
        const uint32_t Ab = (p == 1) ? AL : AH;
        const uint32_t Bb = (p == 2) ? BL : BH;
#pragma unroll
        for (int cb = 0; cb < 4; ++cb) {
            const int c16 = cb * 16;
            uint32_t af[4][4], bf[4][2];
#pragma unroll
            for (int mt = 0; mt < 4; ++mt) {
                uint32_t off = (Ab + (uint32_t)(c16 + tra_r) * KVS + wm * 64 + mt * 16 + tra_c) * 2;
                ldsm_x4t(af[mt][0], af[mt][1], af[mt][2], af[mt][3], sb + off);
            }
#pragma unroll
            for (int g = 0; g < 2; ++g) {
                uint32_t off = (Bb + (uint32_t)(c16 + trb_r) * KVS + wn * 32 + g * 16 + trb_c) * 2;
                ldsm_x4t(bf[2 * g][0], bf[2 * g][1], bf[2 * g + 1][0], bf[2 * g + 1][1], sb + off);
            }
#pragma unroll
            for (int mt = 0; mt < 4; ++mt)
#pragma unroll
                for (int nt = 0; nt < 4; ++nt)
                    mma16816(acc[mt][nt], af[mt], bf[nt]);
        }
    }

#pragma unroll
    for (int mt = 0; mt < 4; ++mt)
#pragma unroll
        for (int nt = 0; nt < 4; ++nt) {
            int row = d0 + wm * 64 + mt * 16 + (lane >> 2);
            int col = vv0 + wn * 32 + nt * 8 + (lane & 3) * 2;
            size_t p0 = ((size_t)unit * 256 + row) * 512 + col;
            *(float2*)&d_U[p0]                 = make_float2(acc[mt][nt][0], acc[mt][nt][1]);
            *(float2*)&d_U[p0 + (size_t)8*512] = make_float2(acc[mt][nt][2], acc[mt][nt][3]);
        }
}

// ---------------- Phase B: decay scan U_n -> prefix states (emit hi/lo) ------
__global__ void scan_kernel()
{
    int bh = blockIdx.x >> 9;
    int e = ((blockIdx.x & 511) << 8) + threadIdx.x;
    int h = bh & 7;
    float logb = logf(1.0f - exp2f(-5.0f - (float)h));
    float cd = expf(logb * 64.0f);
    size_t base = (size_t)bh * (32u * 131072u) + e;
    float p = 0.f;
#pragma unroll
    for (int n = 0; n < 32; ++n) {
        size_t idx = base + (size_t)n * 131072;
        float u = d_U[idx];
        __nv_bfloat16 hp = __float2bfloat16(p);
        sUh[idx] = hp;
        sUl[idx] = __float2bfloat16(p - __bfloat162float(hp));
        p = p * cd + u;
    }
}

// ---------------- scores: Dmask ∘ (Q @ K^T), emits hi/lo ---------------------
__global__ __launch_bounds__(256)
void scores_kernel()
{
    __shared__ float Qs[32][68];
    __shared__ float Ks[32][68];
    const int unit = blockIdx.x;
    const int bh = unit >> 5, n = unit & 31;
    const int b = bh >> 3, h = bh & 7;
    const int bt0 = b * TT + n * 64;
    const float logb = logf(1.0f - exp2f(-5.0f - (float)h));
    const int tid = threadIdx.x, tx = tid & 15, ty = tid >> 4;

    float acc[4][4];
#pragma unroll
    for (int i = 0; i < 4; ++i)
#pragma unroll
        for (int j = 0; j < 4; ++j) acc[i][j] = 0.f;

    for (int k0 = 0; k0 < 256; k0 += 32) {
#pragma unroll
        for (int l = 0; l < 2; ++l) {
            int idx = tid + l * 256;
            int row = idx >> 3;
            int kq = (idx & 7) * 4;
            float4 qv = *(const float4*)&d_q[(size_t)(bt0 + row) * 2048 + h * 256 + k0 + kq];
            Qs[kq + 0][row] = qv.x; Qs[kq + 1][row] = qv.y;
            Qs[kq + 2][row] = qv.z; Qs[kq + 3][row] = qv.w;
            float4 kv = *(const float4*)&d_k[(size_t)(bt0 + row) * 2048 + h * 256 + k0 + kq];
            Ks[kq + 0][row] = kv.x; Ks[kq + 1][row] = kv.y;
            Ks[kq + 2][row] = kv.z; Ks[kq + 3][row] = kv.w;
        }
        __syncthreads();
#pragma unroll
        for (int kk = 0; kk < 32; ++kk) {
            float4 ra = *(const float4*)&Qs[kk][ty * 4];
            float4 rb = *(const float4*)&Ks[kk][tx * 4];
            float a4[4] = {ra.x, ra.y, ra.z, ra.w};
            float b4[4] = {rb.x, rb.y, rb.z, rb.w};
#pragma unroll
            for (int i = 0; i < 4; ++i)
#pragma unroll
                for (int j = 0; j < 4; ++j) acc[i][j] = fmaf(a4[i], b4[j], acc[i][j]);
        }
        __syncthreads();
    }
#pragma unroll
    for (int ii = 0; ii < 4; ++ii)
#pragma unroll
        for (int jj = 0; jj < 4; ++jj) {
            int i = ty * 4 + ii, j = tx * 4 + jj, m = i - j;
            float val = (m >= 0) ? acc[ii][jj] * expf(logb * (float)m) : 0.f;
            split_store(sSch, sScl, (size_t)unit * 4096 + i * 64 + j, val);
        }
}

// =====================================================================
// Phase C (tensor): o = (q∘q_dec)@S_n + scores@V. One barrier per step.
// =====================================================================
#define COA 40
#define COB 264

__global__ __launch_bounds__(256)
void chunk_out_tc()
{
    __shared__ __nv_bfloat16 Asm[2 * 64 * COA];
    __shared__ __nv_bfloat16 Bsm[2 * 32 * COB];
    const int tid = threadIdx.x;
    const int warp = tid >> 5, lane = tid & 31;
    const int wm = warp >> 2, wn = warp & 3;
    const int vv0 = blockIdx.x * 256;
    const int unit = blockIdx.y;
    const int bh = unit >> 5, n = unit & 31;
    const int b = bh >> 3, h = bh & 7;
    const int bt0 = b * TT + n * 64;
    const float logb = logf(1.0f - exp2f(-5.0f - (float)h));
    const uint32_t a0u = (uint32_t)__cvta_generic_to_shared(Asm);
    const uint32_t b0u = (uint32_t)__cvta_generic_to_shared(Bsm);

    float acc[2][8][4];
#pragma unroll
    for (int i = 0; i < 2; ++i)
#pragma unroll
        for (int j = 0; j < 8; ++j)
#pragma unroll
            for (int e = 0; e < 4; ++e) acc[i][j][e] = 0.f;

    auto issue = [&](int j) {
        const __nv_bfloat16 *Ap, *Bp;
        int Astr, Bstr;
        if (j < 24) {
            int p = j >> 3, kk = (j & 7) * 32;
            Ap = ((p == 1) ? sQl : sQh) + (size_t)bt0 * 2048 + h * 256 + kk;  Astr = 2048;
            Bp = ((p == 2) ? sUl : sUh) + ((size_t)unit * 256 + kk) * 512 + vv0; Bstr = 512;
        } else {
            int j2 = j - 24, p = j2 >> 1, kk = (j2 & 1) * 32;
            Ap = ((p == 1) ? sScl : sSch) + (size_t)unit * 4096 + kk;  Astr = 64;
            Bp = ((p == 2) ? sVl : sVh) + (size_t)(bt0 + kk) * 4096 + h * 512 + vv0; Bstr = 4096;
        }
        int s = j & 1;
        {
            int r = tid >> 2, ch = tid & 3;
            cp16(a0u + (uint32_t)(s * 64 * COA + r * COA + ch * 8) * 2, Ap + (size_t)r * Astr + ch * 8);
        }
#pragma unroll
        for (int l = 0; l < 4; ++l) {
            int idx = tid + l * 256;
            int r = idx >> 5, ch = idx & 31;
            cp16(b0u + (uint32_t)(s * 32 * COB + r * COB + ch * 8) * 2, Bp + (size_t)r * Bstr + ch * 8);
        }
        asm volatile("cp.async.commit_group;\n");
    };

    const int a_r = lane & 15, a_c8 = (lane >> 4) << 3;
    const int tb_r = lane & 15, tb_c8 = (lane >> 4) << 3;

    issue(0);
    for (int i = 0; i < 30; ++i) {
        asm volatile("cp.async.wait_group 0;\n");
        __syncthreads();
        if (i + 1 < 30) issue(i + 1);

        const int s = i & 1;
        const uint32_t ab = a0u + (uint32_t)(s * 64 * COA) * 2;
        const uint32_t bb = b0u + (uint32_t)(s * 32 * COB) * 2;
#pragma unroll
        for (int kh = 0; kh < 2; ++kh) {
            uint32_t af[2][4], bf[8][2];
#pragma unroll
            for (int mt = 0; mt < 2; ++mt) {
                uint32_t off = ((uint32_t)(wm * 32 + mt * 16 + a_r) * COA + kh * 16 + a_c8) * 2;
                ldsm_x4(af[mt][0], af[mt][1], af[mt][2], af[mt][3], ab + off);
            }
#pragma unroll
            for (int ng = 0; ng < 4; ++ng) {
                uint32_t off = ((uint32_t)(kh * 16 + tb_r) * COB + wn * 64 + ng * 16 + tb_c8) * 2;
                ldsm_x4t(bf[2 * ng][0], bf[2 * ng][1], bf[2 * ng + 1][0], bf[2 * ng + 1][1], bb + off);
            }
#pragma unroll
            for (int mt = 0; mt < 2; ++mt)
#pragma unroll
                for (int nt = 0; nt < 8; ++nt)
                    mma16816(acc[mt][nt], af[mt], bf[nt]);
        }
        if (i == 23) {
#pragma unroll
            for (int mt = 0; mt < 2; ++mt) {
                float r0 = (float)(wm * 32 + mt * 16 + (lane >> 2));
                float qd0 = expf(logb * (r0 + 1.0f));
                float qd1 = expf(logb * (r0 + 9.0f));
#pragma unroll
                for (int nt = 0; nt < 8; ++nt) {
                    acc[mt][nt][0] *= qd0; acc[mt][nt][1] *= qd0;
                    acc[mt][nt][2] *= qd1; acc[mt][nt][3] *= qd1;
                }
            }
        }
    }

#pragma unroll
    for (int mt = 0; mt < 2; ++mt)
#pragma unroll
        for (int nt = 0; nt < 8; ++nt) {
            int row = bt0 + wm * 32 + mt * 16 + (lane >> 2);
            int col = h * 512 + vv0 + wn * 64 + nt * 8 + (lane & 3) * 2;
            *(float2*)&d_o[(size_t)row * 4096 + col]       = make_float2(acc[mt][nt][0], acc[mt][nt][1]);
            *(float2*)&d_o[(size_t)(row + 8) * 4096 + col] = make_float2(acc[mt][nt][2], acc[mt][nt][3]);
        }
}

// ------- rmsnorm + silu gating, emits bf16 hi/lo directly for the out GEMM ---
__global__ void gate_norm_kernel(const float* __restrict__ gw)
{
    __shared__ float red[4];
    const int row = blockIdx.x;
    const int bt = row >> 3, h = row & 7;
    const size_t base = (size_t)bt * 4096 + h * 512;
    const int tid = threadIdx.x;

    float4 ov = *(const float4*)&d_o[base + tid * 4];
    float ss = ov.x * ov.x + ov.y * ov.y + ov.z * ov.z + ov.w * ov.w;
#pragma unroll
    for (int off = 16; off; off >>= 1) ss += __shfl_xor_sync(0xffffffffu, ss, off);
    if ((tid & 31) == 0) red[tid >> 5] = ss;
    __syncthreads();
    float tot = red[0] + red[1] + red[2] + red[3];
    float inv = rsqrtf(tot * (1.0f / 512.0f) + 1e-5f);

    float4 gv = *(const float4*)&d_g[base + tid * 4];
    float4 w  = *(const float4*)&gw[tid * 4];
    float o0 = ov.x * inv * w.x * (gv.x / (1.f + expf(-gv.x)));
    float o1 = ov.y * inv * w.y * (gv.y / (1.f + expf(-gv.y)));
    float o2 = ov.z * inv * w.z * (gv.z / (1.f + expf(-gv.z)));
    float o3 = ov.w * inv * w.w * (gv.w / (1.f + expf(-gv.w)));

    size_t e = base + tid * 4;
    split_store(sO_h, sO_l, e + 0, o0);
    split_store(sO_h, sO_l, e + 1, o1);
    split_store(sO_h, sO_l, e + 2, o2);
    split_store(sO_h, sO_l, e + 3, o3);
}

// ---------------- launch ------------------------------------------------------
extern "C" void kernel_launch(void* const* d_in, const int* in_sizes, int n_in,
                              void* d_out, int out_size)
{
    const float* X  = (const float*)d_in[0];
    const float* Wq = (const float*)d_in[1];
    const float* Wk = (const float*)d_in[2];
    const float* Wv = (const float*)d_in[3];
    const float* Wg = (const float*)d_in[4];
    const float* Wo = (const float*)d_in[5];
    const float* gw = (const float*)d_in[6];
    float* out = (float*)d_out;

    float *q, *k, *v, *g;
    cudaGetSymbolAddress((void**)&q, d_q);
    cudaGetSymbolAddress((void**)&k, d_k);
    cudaGetSymbolAddress((void**)&v, d_v);
    cudaGetSymbolAddress((void**)&g, d_g);

    __nv_bfloat16 *xh, *xl, *wqh, *wql, *wkh, *wkl, *wvh, *wvl, *wgh, *wgl, *woh, *wol, *oh, *ol, *vh, *vl;
    cudaGetSymbolAddress((void**)&xh, sX_h);   cudaGetSymbolAddress((void**)&xl, sX_l);
    cudaGetSymbolAddress((void**)&wqh, sWq_h); cudaGetSymbolAddress((void**)&wql, sWq_l);
    cudaGetSymbolAddress((void**)&wkh, sWk_h); cudaGetSymbolAddress((void**)&wkl, sWk_l);
    cudaGetSymbolAddress((void**)&wvh, sWv_h); cudaGetSymbolAddress((void**)&wvl, sWv_l);
    cudaGetSymbolAddress((void**)&wgh, sWg_h); cudaGetSymbolAddress((void**)&wgl, sWg_l);
    cudaGetSymbolAddress((void**)&woh, sWo_h); cudaGetSymbolAddress((void**)&wol, sWo_l);
    cudaGetSymbolAddress((void**)&oh, sO_h);   cudaGetSymbolAddress((void**)&ol, sO_l);
    cudaGetSymbolAddress((void**)&vh, sVh);    cudaGetSymbolAddress((void**)&vl, sVl);

    cudaFuncSetAttribute(gemm_bf16v, cudaFuncAttributeMaxDynamicSharedMemorySize, PSMEM);
    cudaFuncSetAttribute(chunk_kv_tc, cudaFuncAttributeMaxDynamicSharedMemorySize, 4 * 64 * KVS * 2);

    rope_table_kernel<<<1024, 256>>>();

    // one-time splits
    split_kernel<<<8192, 256>>>(X,  xh,  xl,  2097152);
    split_kernel<<<4096, 256>>>(Wq, wqh, wql, 1048576);
    split_kernel<<<4096, 256>>>(Wk, wkh, wkl, 1048576);
    split_kernel<<<8192, 256>>>(Wv, wvh, wvl, 2097152);
    split_kernel<<<8192, 256>>>(Wg, wgh, wgl, 2097152);
    split_kernel<<<8192, 256>>>(Wo, woh, wol, 2097152);

    // Projections (split-bf16 mma.sync, 3-stage single-barrier pipeline)
    gemm_bf16v<<<dim3(16, 32), 256, PSMEM>>>(xh, xl, wqh, wql, q, 4096, 2048, 2048);
    gemm_bf16v<<<dim3(16, 32), 256, PSMEM>>>(xh, xl, wkh, wkl, k, 4096, 2048, 2048);
    gemm_bf16v<<<dim3(32, 32), 256, PSMEM>>>(xh, xl, wvh, wvl, v, 4096, 4096, 2048);
    gemm_bf16v<<<dim3(32, 32), 256, PSMEM>>>(xh, xl, wgh, wgl, g, 4096, 4096, 2048);

    rope_kernel<<<16384, 256>>>();
    split_kernel<<<16384, 256>>>(v, vh, vl, 4194304);

    chunk_kv_tc<<<dim3(8, 512), 256, 4 * 64 * KVS * 2>>>();
    scan_kernel<<<8192, 256>>>();
    scores_kernel<<<512, 256>>>();
    chunk_out_tc<<<dim3(2, 512), 256>>>();

    gate_norm_kernel<<<32768, 128>>>(gw);

    gemm_bf16v<<<dim3(16, 32), 256, PSMEM>>>(oh, ol, woh, wol, out, 4096, 2048, 4096);
}

// round 12
// speedup vs baseline: 2.4956x; 1.1162x over previous
#include <cuda_runtime.h>
#include <cuda_bf16.h>
#include <math.h>
#include <stdint.h>

// Problem constants: B=2, T=2048, D=2048, H=8, DK=256, DV=512, C=64, N=32
#define TT 2048

// ---------------- scratch (static device memory; no allocs allowed) ----------
__device__ float d_q[(size_t)4096 * 2048];
__device__ float d_k[(size_t)4096 * 2048];
__device__ float d_v[(size_t)4096 * 4096];
__device__ float d_g[(size_t)4096 * 4096];
__device__ float d_o[(size_t)4096 * 4096];
__device__ float d_U[(size_t)512 * 256 * 512]; // per-chunk KV (fp32, phase A out)
__device__ float d_ropec[2048 * 128];
__device__ float d_ropes[2048 * 128];

// bf16 hi/lo split operands for tensor-core GEMMs
__device__ __nv_bfloat16 sX_h[(size_t)4096 * 2048],  sX_l[(size_t)4096 * 2048];
__device__ __nv_bfloat16 sWq_h[(size_t)2048 * 2048], sWq_l[(size_t)2048 * 2048];
__device__ __nv_bfloat16 sWk_h[(size_t)2048 * 2048], sWk_l[(size_t)2048 * 2048];
__device__ __nv_bfloat16 sWv_h[(size_t)4096 * 2048], sWv_l[(size_t)4096 * 2048];
__device__ __nv_bfloat16 sWg_h[(size_t)4096 * 2048], sWg_l[(size_t)4096 * 2048];
__device__ __nv_bfloat16 sWo_h[(size_t)2048 * 4096], sWo_l[(size_t)2048 * 4096];
__device__ __nv_bfloat16 sO_h[(size_t)4096 * 4096],  sO_l[(size_t)4096 * 4096];

// phase operands (hi/lo)
__device__ __nv_bfloat16 sQh[(size_t)4096 * 2048],  sQl[(size_t)4096 * 2048];   // q post-rope, /16
__device__ __nv_bfloat16 sKdh[(size_t)4096 * 2048], sKdl[(size_t)4096 * 2048];  // k*k_dec
__device__ __nv_bfloat16 sVh[(size_t)4096 * 4096],  sVl[(size_t)4096 * 4096];
__device__ __nv_bfloat16 sUh[(size_t)512 * 256 * 512], sUl[(size_t)512 * 256 * 512]; // prefix states
__device__ __nv_bfloat16 sSch[(size_t)512 * 64 * 64], sScl[(size_t)512 * 64 * 64];   // decayed scores

// ---------------- fp32 -> bf16 hi/lo split (one-time per operand) ------------
__global__ void split_kernel(const float* __restrict__ src,
                             __nv_bfloat16* __restrict__ hi,
                             __nv_bfloat16* __restrict__ lo, int n4)
{
    int i = blockIdx.x * blockDim.x + threadIdx.x;
    if (i >= n4) return;
    float4 v = ((const float4*)src)[i];
    __nv_bfloat16 hx = __float2bfloat16(v.x), hy = __float2bfloat16(v.y);
    __nv_bfloat16 hz = __float2bfloat16(v.z), hw = __float2bfloat16(v.w);
    ((__nv_bfloat162*)hi)[i * 2]     = __halves2bfloat162(hx, hy);
    ((__nv_bfloat162*)hi)[i * 2 + 1] = __halves2bfloat162(hz, hw);
    ((__nv_bfloat162*)lo)[i * 2]     = __halves2bfloat162(
        __float2bfloat16(v.x - __bfloat162float(hx)), __float2bfloat16(v.y - __bfloat162float(hy)));
    ((__nv_bfloat162*)lo)[i * 2 + 1] = __halves2bfloat162(
        __float2bfloat16(v.z - __bfloat162float(hz)), __float2bfloat16(v.w - __bfloat162float(hw)));
}

// ---------------- mma/ldsm/cp.async primitives --------------------------------
__device__ __forceinline__ void ldsm_x4(uint32_t& r0, uint32_t& r1, uint32_t& r2, uint32_t& r3, uint32_t addr) {
    asm volatile("ldmatrix.sync.aligned.m8n8.x4.shared.b16 {%0,%1,%2,%3}, [%4];\n"
                 : "=r"(r0), "=r"(r1), "=r"(r2), "=r"(r3) : "r"(addr));
}
__device__ __forceinline__ void ldsm_x4t(uint32_t& r0, uint32_t& r1, uint32_t& r2, uint32_t& r3, uint32_t addr) {
    asm volatile("ldmatrix.sync.aligned.m8n8.x4.trans.shared.b16 {%0,%1,%2,%3}, [%4];\n"
                 : "=r"(r0), "=r"(r1), "=r"(r2), "=r"(r3) : "r"(addr));
}
__device__ __forceinline__ void mma16816(float* c, const uint32_t* a, const uint32_t* b) {
    asm volatile("mma.sync.aligned.m16n8k16.row.col.f32.bf16.bf16.f32 "
                 "{%0,%1,%2,%3},{%4,%5,%6,%7},{%8,%9},{%0,%1,%2,%3};\n"
                 : "+f"(c[0]), "+f"(c[1]), "+f"(c[2]), "+f"(c[3])
                 : "r"(a[0]), "r"(a[1]), "r"(a[2]), "r"(a[3]), "r"(b[0]), "r"(b[1]));
}
__device__ __forceinline__ void cp16(uint32_t dst, const void* src) {
    asm volatile("cp.async.cg.shared.global [%0], [%1], 16;\n" :: "r"(dst), "l"(src));
}

// =====================================================================
// GEMM core: C[bm:bm+128, bn:bn+128] += A[M,K]*B[N,K]^T over virtual K'=3K.
// 3-stage cp.async ring, one barrier per k-step.
// =====================================================================
#define GSTRIDE 40
#define PSTAGE_BYTES (128 * GSTRIDE * 2)      // 10240 B per operand tile
#define PSMEM (3 * 2 * PSTAGE_BYTES)          // 61440 B

extern __shared__ __nv_bfloat16 dynsm[];

__device__ __forceinline__ void gemm_core(
    const __nv_bfloat16* __restrict__ Ah, const __nv_bfloat16* __restrict__ Al,
    const __nv_bfloat16* __restrict__ Bh, const __nv_bfloat16* __restrict__ Bl,
    float* __restrict__ C, int bm, int bn, int Nloc, int K)
{
    const int tid = threadIdx.x;
    const int warp = tid >> 5, lane = tid & 31;
    const int wm = warp >> 2, wn = warp & 3;
    const int kseg = K >> 5, nk = 3 * kseg;

    const uint32_t s0 = (uint32_t)__cvta_generic_to_shared(dynsm);
    const int p_row = tid >> 2, p_ch = (tid & 3) << 3;

    float acc[4][4][4];
#pragma unroll
    for (int i = 0; i < 4; ++i)
#pragma unroll
        for (int j = 0; j < 4; ++j)
#pragma unroll
            for (int e = 0; e < 4; ++e) acc[i][j][e] = 0.f;

    const int a_r = (lane & 15), a_c8 = ((lane >> 4) << 3);
    const int b_r = ((lane >> 4) << 3) + (lane & 7), b_c8 = (((lane >> 3) & 1) << 3);

    auto issue = [&](int ks) {
        int seg = (ks >= kseg) + (ks >= 2 * kseg);
        const __nv_bfloat16* Asel = (seg == 1) ? Al : Ah;
        const __nv_bfloat16* Bsel = (seg == 2) ? Bl : Bh;
        int k0 = (ks - seg * kseg) << 5;
        int s = ks % 3;
        uint32_t ab = s0 + (uint32_t)s * (2 * PSTAGE_BYTES);
#pragma unroll
        for (int l = 0; l < 2; ++l) {
            int row = p_row + l * 64;
            uint32_t soff = (uint32_t)(row * GSTRIDE + p_ch) * 2;
            cp16(ab + soff, Asel + (size_t)(bm + row) * K + k0 + p_ch);
            cp16(ab + PSTAGE_BYTES + soff, Bsel + (size_t)(bn + row) * K + k0 + p_ch);
        }
        asm volatile("cp.async.commit_group;\n");
    };

    issue(0);
    issue(1);
    for (int ks = 0; ks < nk; ++ks) {
        if (ks + 1 < nk)
            asm volatile("cp.async.wait_group 1;\n");
        else
            asm volatile("cp.async.wait_group 0;\n");
        __syncthreads();
        if (ks + 2 < nk) issue(ks + 2);

        const int s = ks % 3;
        const uint32_t sa = s0 + (uint32_t)s * (2 * PSTAGE_BYTES);
        const uint32_t sb = sa + PSTAGE_BYTES;
#pragma unroll
        for (int kh = 0; kh < 2; ++kh) {
            uint32_t af[4][4], bf[4][2];
#pragma unroll
            for (int mt = 0; mt < 4; ++mt) {
                int off = ((wm * 64 + mt * 16 + a_r) * GSTRIDE + kh * 16 + a_c8) * 2;
                ldsm_x4(af[mt][0], af[mt][1], af[mt][2], af[mt][3], sa + off);
            }
#pragma unroll
            for (int p = 0; p < 2; ++p) {
                int off = ((wn * 32 + p * 16 + b_r) * GSTRIDE + kh * 16 + b_c8) * 2;
                ldsm_x4(bf[2 * p][0], bf[2 * p][1], bf[2 * p + 1][0], bf[2 * p + 1][1], sb + off);
            }
#pragma unroll
            for (int mt = 0; mt < 4; ++mt)
#pragma unroll
                for (int nt = 0; nt < 4; ++nt)
                    mma16816(acc[mt][nt], af[mt], bf[nt]);
        }
    }

#pragma unroll
    for (int mt = 0; mt < 4; ++mt)
#pragma unroll
        for (int nt = 0; nt < 4; ++nt) {
            int row = bm + wm * 64 + mt * 16 + (lane >> 2);
            int col = bn + wn * 32 + nt * 8 + (lane & 3) * 2;
            *(float2*)(C + (size_t)row * Nloc + col)       = make_float2(acc[mt][nt][0], acc[mt][nt][1]);
            *(float2*)(C + (size_t)(row + 8) * Nloc + col) = make_float2(acc[mt][nt][2], acc[mt][nt][3]);
        }
}

// generic (used for the output projection)
__global__ __launch_bounds__(256, 2)
void gemm_bf16v(const __nv_bfloat16* __restrict__ Ah, const __nv_bfloat16* __restrict__ Al,
                const __nv_bfloat16* __restrict__ Bh, const __nv_bfloat16* __restrict__ Bl,
                float* __restrict__ C, int M, int N, int K)
{
    gemm_core(Ah, Al, Bh, Bl, C, blockIdx.y * 128, blockIdx.x * 128, N, K);
}

// merged q/k/v/g projection GEMM: one launch, block-uniform routing by column
__global__ __launch_bounds__(256, 2)
void gemm_qkvg(const __nv_bfloat16* __restrict__ xh, const __nv_bfloat16* __restrict__ xl,
               const __nv_bfloat16* __restrict__ wqh, const __nv_bfloat16* __restrict__ wql,
               const __nv_bfloat16* __restrict__ wkh, const __nv_bfloat16* __restrict__ wkl,
               const __nv_bfloat16* __restrict__ wvh, const __nv_bfloat16* __restrict__ wvl,
               const __nv_bfloat16* __restrict__ wgh, const __nv_bfloat16* __restrict__ wgl,
               float* __restrict__ q, float* __restrict__ k,
               float* __restrict__ v, float* __restrict__ g)
{
    const int bng = blockIdx.x * 128;    // 0..12287
    const __nv_bfloat16 *Bh, *Bl;
    float* C;
    int Nloc, bn;
    if (bng < 2048)      { Bh = wqh; Bl = wql; C = q; Nloc = 2048; bn = bng; }
    else if (bng < 4096) { Bh = wkh; Bl = wkl; C = k; Nloc = 2048; bn = bng - 2048; }
    else if (bng < 8192) { Bh = wvh; Bl = wvl; C = v; Nloc = 4096; bn = bng - 4096; }
    else                 { Bh = wgh; Bl = wgl; C = g; Nloc = 4096; bn = bng - 8192; }
    gemm_core(xh, xl, Bh, Bl, C, blockIdx.y * 128, bn, Nloc, 2048);
}

// ---------------- RoPE table -------------------------------------------------
__global__ void rope_table_kernel()
{
    int idx = blockIdx.x * blockDim.x + threadIdx.x;
    int i = idx & 127, t = idx >> 7;
    double invf_d = exp(-(double)i * (9.210340371976184 / 128.0));
    float phase = (float)t * (float)invf_d;
    double sd, cd;
    sincos((double)phase, &sd, &cd);
    d_ropec[idx] = (float)cd;
    d_ropes[idx] = (float)sd;
}

__device__ __forceinline__ void split_store(__nv_bfloat16* hi, __nv_bfloat16* lo, size_t i, float x) {
    __nv_bfloat16 h = __float2bfloat16(x);
    hi[i] = h;
    lo[i] = __float2bfloat16(x - __bfloat162float(h));
}

// ---------------- RoPE: q (scaled 1/16) and k; emit fp32 + hi/lo -------------
__global__ void rope_kernel()
{
    int idx = blockIdx.x * blockDim.x + threadIdx.x;   // < 4096*8*128
    int i = idx & 127;
    int h = (idx >> 7) & 7;
    int bt = idx >> 10;
    int t = bt & (TT - 1);
    float c = d_ropec[(t << 7) + i], s = d_ropes[(t << 7) + i];

    size_t base = (size_t)bt * 2048 + h * 256 + i;
    float x1 = d_q[base], x2 = d_q[base + 128];
    float q1 = (x1 * c - x2 * s) * 0.0625f;
    float q2 = (x2 * c + x1 * s) * 0.0625f;
    d_q[base] = q1; d_q[base + 128] = q2;
    split_store(sQh, sQl, base, q1);
    split_store(sQh, sQl, base + 128, q2);

    x1 = d_k[base]; x2 = d_k[base + 128];
    float k1 = x1 * c - x2 * s;
    float k2 = x2 * c + x1 * s;
    d_k[base] = k1; d_k[base + 128] = k2;

    float logb = logf(1.0f - exp2f(-5.0f - (float)h));
    float kd = expf(logb * (float)(63 - (t & 63)));
    split_store(sKdh, sKdl, base, k1 * kd);
    split_store(sKdh, sKdl, base + 128, k2 * kd);
}

// =====================================================================
// Phase A (tensor): U[unit] = (k∘k_dec)^T @ v, 3-pass split-bf16.
// =====================================================================
#define KVS 136    // smem row stride (bf16); 272B == 4 words mod 32 -> conflict-free

__global__ void chunk_kv_tc()
{
    const int tid = threadIdx.x;
    const int warp = tid >> 5, lane = tid & 31;
    const int wm = warp >> 2, wn = warp & 3;
    const int d0 = (blockIdx.x >> 2) * 128, vv0 = (blockIdx.x & 3) * 128;
    const int unit = blockIdx.y;
    const int bh = unit >> 5, n = unit & 31;
    const int b = bh >> 3, h = bh & 7;
    const int bt0 = b * TT + n * 64;
    const uint32_t sb = (uint32_t)__cvta_generic_to_shared(dynsm);
    const uint32_t AH = 0, AL = 64 * KVS, BH = 2 * 64 * KVS, BL = 3 * 64 * KVS;

#pragma unroll
    for (int l = 0; l < 16; ++l) {
        int idx = tid + l * 256;
        int t = idx >> 10, r = (idx >> 4) & 63, ch = idx & 15;
        const __nv_bfloat16* src;
        if (t == 0)      src = sKdh + (size_t)(bt0 + r) * 2048 + h * 256 + d0 + ch * 8;
        else if (t == 1) src = sKdl + (size_t)(bt0 + r) * 2048 + h * 256 + d0 + ch * 8;
        else if (t == 2) src = sVh  + (size_t)(bt0 + r) * 4096 + h * 512 + vv0 + ch * 8;
        else             src = sVl  + (size_t)(bt0 + r) * 4096 + h * 512 + vv0 + ch * 8;
        cp16(sb + (uint32_t)(t * 64 * KVS + r * KVS + ch * 8) * 2, src);
    }
    asm volatile("cp.async.commit_group;\ncp.async.wait_group 0;\n");
    __syncthreads();

    float acc[4][4][4];
#pragma unroll
    for (int i = 0; i < 4; ++i)
#pragma unroll
        for (int j = 0; j < 4; ++j)
#pragma unroll
            for (int e = 0; e < 4; ++e) acc[i][j][e] = 0.f;

    const int tra_r = (lane & 7) + (((lane >> 4) & 1) << 3);
    const int tra_c = ((lane >> 3) & 1) << 3;
    const int trb_r = lane & 15;
    const int trb_c = (lane >> 4) << 3;

#pragma unroll
    for (int p = 0; p < 3; ++p) {
        const uint32_t Ab = (p == 1) ? AL : AH;
        const uint32_t Bb = (p == 2) ? BL : BH;
#pragma unroll
        for (int cb = 0; cb < 4; ++cb) {
            const int c16 = cb * 16;
            uint32_t af[4][4], bf[4][2];
#pragma unroll
            for (int mt = 0; mt < 4; ++mt) {
                uint32_t off = (Ab + (uint32_t)(c16 + tra_r) * KVS + wm * 64 + mt * 16 + tra_c) * 2;
                ldsm_x4t(af[mt][0], af[mt][1], af[mt][2], af[mt][3], sb + off);
            }
#pragma unroll
            for (int g = 0; g < 2; ++g) {
                uint32_t off = (Bb + (uint32_t)(c16 + trb_r) * KVS + wn * 32 + g * 16 + trb_c) * 2;
                ldsm_x4t(bf[2 * g][0], bf[2 * g][1], bf[2 * g + 1][0], bf[2 * g + 1][1], sb + off);
            }
#pragma unroll
            for (int mt = 0; mt < 4; ++mt)
#pragma unroll
                for (int nt = 0; nt < 4; ++nt)
                    mma16816(acc[mt][nt], af[mt], bf[nt]);
        }
    }

#pragma unroll
    for (int mt = 0; mt < 4; ++mt)
#pragma unroll
        for (int nt = 0; nt < 4; ++nt) {
            int row = d0 + wm * 64 + mt * 16 + (lane >> 2);
            int col = vv0 + wn * 32 + nt * 8 + (lane & 3) * 2;
            size_t p0 = ((size_t)unit * 256 + row) * 512 + col;
            *(float2*)&d_U[p0]                 = make_float2(acc[mt][nt][0], acc[mt][nt][1]);
            *(float2*)&d_U[p0 + (size_t)8*512] = make_float2(acc[mt][nt][2], acc[mt][nt][3]);
        }
}

// ---------------- Phase B: decay scan U_n -> prefix states (emit hi/lo) ------
__global__ void scan_kernel()
{
    int bh = blockIdx.x >> 9;
    int e = ((blockIdx.x & 511) << 8) + threadIdx.x;
    int h = bh & 7;
    float logb = logf(1.0f - exp2f(-5.0f - (float)h));
    float cd = expf(logb * 64.0f);
    size_t base = (size_t)bh * (32u * 131072u) + e;
    float p = 0.f;
#pragma unroll
    for (int n = 0; n < 32; ++n) {
        size_t idx = base + (size_t)n * 131072;
        float u = d_U[idx];
        __nv_bfloat16 hp = __float2bfloat16(p);
        sUh[idx] = hp;
        sUl[idx] = __float2bfloat16(p - __bfloat162float(hp));
        p = p * cd + u;
    }
}

// ---------------- scores: Dmask ∘ (Q @ K^T), emits hi/lo ---------------------
__global__ __launch_bounds__(256)
void scores_kernel()
{
    __shared__ float Qs[32][68];
    __shared__ float Ks[32][68];
    const int unit = blockIdx.x;
    const int bh = unit >> 5, n = unit & 31;
    const int b = bh >> 3, h = bh & 7;
    const int bt0 = b * TT + n * 64;
    const float logb = logf(1.0f - exp2f(-5.0f - (float)h));
    const int tid = threadIdx.x, tx = tid & 15, ty = tid >> 4;

    float acc[4][4];
#pragma unroll
    for (int i = 0; i < 4; ++i)
#pragma unroll
        for (int j = 0; j < 4; ++j) acc[i][j] = 0.f;

    for (int k0 = 0; k0 < 256; k0 += 32) {
#pragma unroll
        for (int l = 0; l < 2; ++l) {
            int idx = tid + l * 256;
            int row = idx >> 3;
            int kq = (idx & 7) * 4;
            float4 qv = *(const float4*)&d_q[(size_t)(bt0 + row) * 2048 + h * 256 + k0 + kq];
            Qs[kq + 0][row] = qv.x; Qs[kq + 1][row] = qv.y;
            Qs[kq + 2][row] = qv.z; Qs[kq + 3][row] = qv.w;
            float4 kv = *(const float4*)&d_k[(size_t)(bt0 + row) * 2048 + h * 256 + k0 + kq];
            Ks[kq + 0][row] = kv.x; Ks[kq + 1][row] = kv.y;
            Ks[kq + 2][row] = kv.z; Ks[kq + 3][row] = kv.w;
        }
        __syncthreads();
#pragma unroll
        for (int kk = 0; kk < 32; ++kk) {
            float4 ra = *(const float4*)&Qs[kk][ty * 4];
            float4 rb = *(const float4*)&Ks[kk][tx * 4];
            float a4[4] = {ra.x, ra.y, ra.z, ra.w};
            float b4[4] = {rb.x, rb.y, rb.z, rb.w};
#pragma unroll
            for (int i = 0; i < 4; ++i)
#pragma unroll
                for (int j = 0; j < 4; ++j) acc[i][j] = fmaf(a4[i], b4[j], acc[i][j]);
        }
        __syncthreads();
    }
#pragma unroll
    for (int ii = 0; ii < 4; ++ii)
#pragma unroll
        for (int jj = 0; jj < 4; ++jj) {
            int i = ty * 4 + ii, j = tx * 4 + jj, m = i - j;
            float val = (m >= 0) ? acc[ii][jj] * expf(logb * (float)m) : 0.f;
            split_store(sSch, sScl, (size_t)unit * 4096 + i * 64 + j, val);
        }
}

// =====================================================================
// Phase C (tensor): o = (q∘q_dec)@S_n + scores@V.
// 3-stage cp.async ring, one barrier per step (dynamic smem).
// =====================================================================
#define COA 40
#define COB 264
#define CO_ASZ (64 * COA)                    // elems per A stage
#define CO_BSZ (32 * COB)                    // elems per B stage
#define CO_SMEM ((3 * CO_ASZ + 3 * CO_BSZ) * 2)

__global__ __launch_bounds__(256)
void chunk_out_tc()
{
    const int tid = threadIdx.x;
    const int warp = tid >> 5, lane = tid & 31;
    const int wm = warp >> 2, wn = warp & 3;
    const int vv0 = blockIdx.x * 256;
    const int unit = blockIdx.y;
    const int bh = unit >> 5, n = unit & 31;
    const int b = bh >> 3, h = bh & 7;
    const int bt0 = b * TT + n * 64;
    const float logb = logf(1.0f - exp2f(-5.0f - (float)h));
    const uint32_t a0u = (uint32_t)__cvta_generic_to_shared(dynsm);
    const uint32_t b0u = a0u + 3 * CO_ASZ * 2;

    float acc[2][8][4];
#pragma unroll
    for (int i = 0; i < 2; ++i)
#pragma unroll
        for (int j = 0; j < 8; ++j)
#pragma unroll
            for (int e = 0; e < 4; ++e) acc[i][j][e] = 0.f;

    auto issue = [&](int j) {
        const __nv_bfloat16 *Ap, *Bp;
        int Astr, Bstr;
        if (j < 24) {
            int p = j >> 3, kk = (j & 7) * 32;
            Ap = ((p == 1) ? sQl : sQh) + (size_t)bt0 * 2048 + h * 256 + kk;  Astr = 2048;
            Bp = ((p == 2) ? sUl : sUh) + ((size_t)unit * 256 + kk) * 512 + vv0; Bstr = 512;
        } else {
            int j2 = j - 24, p = j2 >> 1, kk = (j2 & 1) * 32;
            Ap = ((p == 1) ? sScl : sSch) + (size_t)unit * 4096 + kk;  Astr = 64;
            Bp = ((p == 2) ? sVl : sVh) + (size_t)(bt0 + kk) * 4096 + h * 512 + vv0; Bstr = 4096;
        }
        int s = j % 3;
        {
            int r = tid >> 2, ch = tid & 3;
            cp16(a0u + (uint32_t)(s * CO_ASZ + r * COA + ch * 8) * 2, Ap + (size_t)r * Astr + ch * 8);
        }
#pragma unroll
        for (int l = 0; l < 4; ++l) {
            int idx = tid + l * 256;
            int r = idx >> 5, ch = idx & 31;
            cp16(b0u + (uint32_t)(s * CO_BSZ + r * COB + ch * 8) * 2, Bp + (size_t)r * Bstr + ch * 8);
        }
        asm volatile("cp.async.commit_group;\n");
    };

    const int a_r = lane & 15, a_c8 = (lane >> 4) << 3;
    const int tb_r = lane & 15, tb_c8 = (lane >> 4) << 3;

    issue(0);
    issue(1);
    for (int i = 0; i < 30; ++i) {
        if (i + 1 < 30)
            asm volatile("cp.async.wait_group 1;\n");
        else
            asm volatile("cp.async.wait_group 0;\n");
        __syncthreads();
        if (i + 2 < 30) issue(i + 2);

        const int s = i % 3;
        const uint32_t ab = a0u + (uint32_t)(s * CO_ASZ) * 2;
        const uint32_t bb = b0u + (uint32_t)(s * CO_BSZ) * 2;
#pragma unroll
        for (int kh = 0; kh < 2; ++kh) {
            uint32_t af[2][4], bf[8][2];
#pragma unroll
            for (int mt = 0; mt < 2; ++mt) {
                uint32_t off = ((uint32_t)(wm * 32 + mt * 16 + a_r) * COA + kh * 16 + a_c8) * 2;
                ldsm_x4(af[mt][0], af[mt][1], af[mt][2], af[mt][3], ab + off);
            }
#pragma unroll
            for (int ng = 0; ng < 4; ++ng) {
                uint32_t off = ((uint32_t)(kh * 16 + tb_r) * COB + wn * 64 + ng * 16 + tb_c8) * 2;
                ldsm_x4t(bf[2 * ng][0], bf[2 * ng][1], bf[2 * ng + 1][0], bf[2 * ng + 1][1], bb + off);
            }
#pragma unroll
            for (int mt = 0; mt < 2; ++mt)
#pragma unroll
                for (int nt = 0; nt < 8; ++nt)
                    mma16816(acc[mt][nt], af[mt], bf[nt]);
        }
        if (i == 23) {
#pragma unroll
            for (int mt = 0; mt < 2; ++mt) {
                float r0 = (float)(wm * 32 + mt * 16 + (lane >> 2));
                float qd0 = expf(logb * (r0 + 1.0f));
                float qd1 = expf(logb * (r0 + 9.0f));
#pragma unroll
                for (int nt = 0; nt < 8; ++nt) {
                    acc[mt][nt][0] *= qd0; acc[mt][nt][1] *= qd0;
                    acc[mt][nt][2] *= qd1; acc[mt][nt][3] *= qd1;
                }
            }
        }
    }

#pragma unroll
    for (int mt = 0; mt < 2; ++mt)
#pragma unroll
        for (int nt = 0; nt < 8; ++nt) {
            int row = bt0 + wm * 32 + mt * 16 + (lane >> 2);
            int col = h * 512 + vv0 + wn * 64 + nt * 8 + (lane & 3) * 2;
            *(float2*)&d_o[(size_t)row * 4096 + col]       = make_float2(acc[mt][nt][0], acc[mt][nt][1]);
            *(float2*)&d_o[(size_t)(row + 8) * 4096 + col] = make_float2(acc[mt][nt][2], acc[mt][nt][3]);
        }
}

// ------- rmsnorm + silu gating, emits bf16 hi/lo directly for the out GEMM ---
__global__ void gate_norm_kernel(const float* __restrict__ gw)
{
    __shared__ float red[4];
    const int row = blockIdx.x;
    const int bt = row >> 3, h = row & 7;
    const size_t base = (size_t)bt * 4096 + h * 512;
    const int tid = threadIdx.x;

    float4 ov = *(const float4*)&d_o[base + tid * 4];
    float ss = ov.x * ov.x + ov.y * ov.y + ov.z * ov.z + ov.w * ov.w;
#pragma unroll
    for (int off = 16; off; off >>= 1) ss += __shfl_xor_sync(0xffffffffu, ss, off);
    if ((tid & 31) == 0) red[tid >> 5] = ss;
    __syncthreads();
    float tot = red[0] + red[1] + red[2] + red[3];
    float inv = rsqrtf(tot * (1.0f / 512.0f) + 1e-5f);

    float4 gv = *(const float4*)&d_g[base + tid * 4];
    float4 w  = *(const float4*)&gw[tid * 4];
    float o0 = ov.x * inv * w.x * (gv.x / (1.f + expf(-gv.x)));
    float o1 = ov.y * inv * w.y * (gv.y / (1.f + expf(-gv.y)));
    float o2 = ov.z * inv * w.z * (gv.z / (1.f + expf(-gv.z)));
    float o3 = ov.w * inv * w.w * (gv.w / (1.f + expf(-gv.w)));

    size_t e = base + tid * 4;
    split_store(sO_h, sO_l, e + 0, o0);
    split_store(sO_h, sO_l, e + 1, o1);
    split_store(sO_h, sO_l, e + 2, o2);
    split_store(sO_h, sO_l, e + 3, o3);
}

// ---------------- launch ------------------------------------------------------
extern "C" void kernel_launch(void* const* d_in, const int* in_sizes, int n_in,
                              void* d_out, int out_size)
{
    const float* X  = (const float*)d_in[0];
    const float* Wq = (const float*)d_in[1];
    const float* Wk = (const float*)d_in[2];
    const float* Wv = (const float*)d_in[3];
    const float* Wg = (const float*)d_in[4];
    const float* Wo = (const float*)d_in[5];
    const float* gw = (const float*)d_in[6];
    float* out = (float*)d_out;

    float *q, *k, *v, *g;
    cudaGetSymbolAddress((void**)&q, d_q);
    cudaGetSymbolAddress((void**)&k, d_k);
    cudaGetSymbolAddress((void**)&v, d_v);
    cudaGetSymbolAddress((void**)&g, d_g);

    __nv_bfloat16 *xh, *xl, *wqh, *wql, *wkh, *wkl, *wvh, *wvl, *wgh, *wgl, *woh, *wol, *oh, *ol, *vh, *vl;
    cudaGetSymbolAddress((void**)&xh, sX_h);   cudaGetSymbolAddress((void**)&xl, sX_l);
    cudaGetSymbolAddress((void**)&wqh, sWq_h); cudaGetSymbolAddress((void**)&wql, sWq_l);
    cudaGetSymbolAddress((void**)&wkh, sWk_h); cudaGetSymbolAddress((void**)&wkl, sWk_l);
    cudaGetSymbolAddress((void**)&wvh, sWv_h); cudaGetSymbolAddress((void**)&wvl, sWv_l);
    cudaGetSymbolAddress((void**)&wgh, sWg_h); cudaGetSymbolAddress((void**)&wgl, sWg_l);
    cudaGetSymbolAddress((void**)&woh, sWo_h); cudaGetSymbolAddress((void**)&wol, sWo_l);
    cudaGetSymbolAddress((void**)&oh, sO_h);   cudaGetSymbolAddress((void**)&ol, sO_l);
    cudaGetSymbolAddress((void**)&vh, sVh);    cudaGetSymbolAddress((void**)&vl, sVl);

    cudaFuncSetAttribute(gemm_bf16v, cudaFuncAttributeMaxDynamicSharedMemorySize, PSMEM);
    cudaFuncSetAttribute(gemm_qkvg, cudaFuncAttributeMaxDynamicSharedMemorySize, PSMEM);
    cudaFuncSetAttribute(chunk_kv_tc, cudaFuncAttributeMaxDynamicSharedMemorySize, 4 * 64 * KVS * 2);
    cudaFuncSetAttribute(chunk_out_tc, cudaFuncAttributeMaxDynamicSharedMemorySize, CO_SMEM);

    rope_table_kernel<<<1024, 256>>>();

    // one-time splits
    split_kernel<<<8192, 256>>>(X,  xh,  xl,  2097152);
    split_kernel<<<4096, 256>>>(Wq, wqh, wql, 1048576);
    split_kernel<<<4096, 256>>>(Wk, wkh, wkl, 1048576);
    split_kernel<<<8192, 256>>>(Wv, wvh, wvl, 2097152);
    split_kernel<<<8192, 256>>>(Wg, wgh, wgl, 2097152);
    split_kernel<<<8192, 256>>>(Wo, woh, wol, 2097152);

    // Projections: ONE merged launch (q,k,v,g)
    gemm_qkvg<<<dim3(96, 32), 256, PSMEM>>>(xh, xl, wqh, wql, wkh, wkl,
                                            wvh, wvl, wgh, wgl, q, k, v, g);

    rope_kernel<<<16384, 256>>>();
    split_kernel<<<16384, 256>>>(v, vh, vl, 4194304);

    chunk_kv_tc<<<dim3(8, 512), 256, 4 * 64 * KVS * 2>>>();
    scan_kernel<<<8192, 256>>>();
    scores_kernel<<<512, 256>>>();
    chunk_out_tc<<<dim3(2, 512), 256, CO_SMEM>>>();

    gate_norm_kernel<<<32768, 128>>>(gw);

    gemm_bf16v<<<dim3(16, 32), 256, PSMEM>>>(oh, ol, woh, wol, out, 4096, 2048, 4096);
}